// round 6
// baseline (speedup 1.0000x reference)
#include <cuda_runtime.h>
#include <math.h>
#include <stddef.h>

#define BB 4
#define TT 2048
#define CC 1024
#define HH 16
#define DD 64
#define NTOK (BB*TT)     /* 8192 */
#define C3   (3*CC)      /* 3072 */
#define OUT0_ELEMS ((size_t)BB*TT*CC)   /* 8388608 */

// ---------------- scratch (no allocations allowed) ----------------
__device__ float g_qkv[(size_t)NTOK * C3];        // 100.7 MB
__device__ float g_qn [(size_t)BB*HH*TT*DD];      // 33.5 MB  (rmsnorm+rope'd Q, head-major)
__device__ float g_kn [(size_t)BB*HH*TT*DD];      // 33.5 MB
__device__ float g_vn [(size_t)BB*HH*TT*DD];      // 33.5 MB  (V, head-major)
__device__ float g_attn[(size_t)NTOK * CC];       // 33.5 MB  (attention output, [tok, C])

// ---------------- SGEMM: C = A[MxK] * B[KxN] + bias[N] ----------------
#define GBM 128
#define GBN 128
#define GBK 16

__global__ __launch_bounds__(256, 2) void sgemm_bias_kernel(
    const float* __restrict__ A, const float* __restrict__ Bm,
    const float* __restrict__ bias, float* __restrict__ Cm,
    int M, int N, int K)
{
    __shared__ float As[GBK][GBM];   // transposed A tile
    __shared__ float Bs[GBK][GBN];

    int tid = threadIdx.x;
    int m0 = blockIdx.y * GBM;
    int n0 = blockIdx.x * GBN;
    int tr = tid >> 4;     // 0..15
    int tc = tid & 15;     // 0..15

    float acc[8][8];
#pragma unroll
    for (int i = 0; i < 8; ++i)
#pragma unroll
        for (int j = 0; j < 8; ++j) acc[i][j] = 0.f;

    const float* Ab = A + (size_t)m0 * K;
    const float* Bb = Bm + n0;

    for (int k0 = 0; k0 < K; k0 += GBK) {
#pragma unroll
        for (int it = 0; it < 2; ++it) {
            int id  = tid + it * 256;      // 0..511
            int row = id >> 2;             // 0..127
            int kc  = (id & 3) * 4;        // 0,4,8,12
            float4 a4 = *(const float4*)(Ab + (size_t)row * K + k0 + kc);
            As[kc + 0][row] = a4.x;
            As[kc + 1][row] = a4.y;
            As[kc + 2][row] = a4.z;
            As[kc + 3][row] = a4.w;
        }
#pragma unroll
        for (int it = 0; it < 2; ++it) {
            int id  = tid + it * 256;
            int row = id >> 5;             // 0..15
            int nc  = (id & 31) * 4;       // 0..124
            *(float4*)&Bs[row][nc] = *(const float4*)(Bb + (size_t)(k0 + row) * N + nc);
        }
        __syncthreads();

#pragma unroll
        for (int kk = 0; kk < GBK; ++kk) {
            float a[8], b[8];
            *(float4*)(a)     = *(const float4*)&As[kk][tr * 4];
            *(float4*)(a + 4) = *(const float4*)&As[kk][64 + tr * 4];
            *(float4*)(b)     = *(const float4*)&Bs[kk][tc * 4];
            *(float4*)(b + 4) = *(const float4*)&Bs[kk][64 + tc * 4];
#pragma unroll
            for (int i = 0; i < 8; ++i)
#pragma unroll
                for (int j = 0; j < 8; ++j)
                    acc[i][j] += a[i] * b[j];
        }
        __syncthreads();
    }

#pragma unroll
    for (int ih = 0; ih < 2; ++ih)
#pragma unroll
        for (int ii = 0; ii < 4; ++ii) {
            int r = m0 + ih * 64 + tr * 4 + ii;
#pragma unroll
            for (int jh = 0; jh < 2; ++jh) {
                int c = n0 + jh * 64 + tc * 4;
                float4 o;
                o.x = acc[ih * 4 + ii][jh * 4 + 0] + bias[c + 0];
                o.y = acc[ih * 4 + ii][jh * 4 + 1] + bias[c + 1];
                o.z = acc[ih * 4 + ii][jh * 4 + 2] + bias[c + 2];
                o.w = acc[ih * 4 + ii][jh * 4 + 3] + bias[c + 3];
                *(float4*)(Cm + (size_t)r * N + c) = o;
            }
        }
}

// ---------------- RMSNorm + RoPE (STANDARD sign, validated by round-5 experiment) ----------------
// one warp per (b,h,t): processes the 64-dim q row and k row, copies v.
__global__ __launch_bounds__(256) void rmsrope_kernel(
    const float* __restrict__ qkv,
    float* __restrict__ qn, float* __restrict__ kn, float* __restrict__ vout)
{
    int gw   = (int)((blockIdx.x * blockDim.x + threadIdx.x) >> 5);
    int lane = threadIdx.x & 31;
    if (gw >= BB * HH * TT) return;
    int t = gw % TT;
    int h = (gw / TT) % HH;
    int b = gw / (TT * HH);

    size_t tok = (size_t)b * TT + t;
    const float* base = qkv + tok * C3 + h * DD;
    size_t oidx = ((size_t)(b * HH + h) * TT + t) * DD;

    float ex  = (float)lane * (1.0f / 32.0f);
    float inv = expf(-ex * 9.210340371976184f);   // 10000^(-lane/32)
    float ang = (float)t * inv;
    float cs, sn;
    sincosf(ang, &cs, &sn);

    // q
    {
        float x1 = base[lane], x2 = base[lane + 32];
        float ss = x1 * x1 + x2 * x2;
#pragma unroll
        for (int off = 16; off; off >>= 1) ss += __shfl_xor_sync(0xffffffffu, ss, off);
        float r = rsqrtf(ss * (1.0f / 64.0f) + 1e-6f);
        x1 *= r; x2 *= r;
        qn[oidx + lane]      = x1 * cs - x2 * sn;   // standard rotation
        qn[oidx + lane + 32] = x1 * sn + x2 * cs;
    }
    // k
    {
        const float* kb = base + CC;
        float x1 = kb[lane], x2 = kb[lane + 32];
        float ss = x1 * x1 + x2 * x2;
#pragma unroll
        for (int off = 16; off; off >>= 1) ss += __shfl_xor_sync(0xffffffffu, ss, off);
        float r = rsqrtf(ss * (1.0f / 64.0f) + 1e-6f);
        x1 *= r; x2 *= r;
        kn[oidx + lane]      = x1 * cs - x2 * sn;
        kn[oidx + lane + 32] = x1 * sn + x2 * cs;
    }
    // v (lamb is an exact identity)
    vout[oidx + lane]      = base[2 * CC + lane];
    vout[oidx + lane + 32] = base[2 * CC + lane + 32];
}

// ---------------- value copy ----------------
__global__ __launch_bounds__(256) void copy_kernel(
    const float* __restrict__ src, float* __restrict__ dst, size_t n4)
{
    size_t i = (size_t)blockIdx.x * blockDim.x + threadIdx.x;
    if (i < n4) ((float4*)dst)[i] = ((const float4*)src)[i];
}

// ---------------- flash attention, fp32, 64x64 tiles ----------------
#define KSTR 68
#define FL_SMEM (3 * 64 * KSTR * 4)   /* 52224 bytes */

__global__ __launch_bounds__(256) void flash_kernel(
    const float* __restrict__ qn, const float* __restrict__ kn,
    const float* __restrict__ vv, float* __restrict__ attn)
{
    extern __shared__ float sm[];
    float* Qs = sm;                 // 64 x 68 (scaled by 1/8)
    float* Ks = sm + 64 * KSTR;     // 64 x 68, later aliased as P
    float* Vs = sm + 2 * 64 * KSTR; // 64 x 68

    int qtile = blockIdx.x;         // 0..31
    int bh    = blockIdx.y;         // 0..63
    int tid = threadIdx.x;
    int tx = tid & 15, ty = tid >> 4;

    const float* qb = qn + (((size_t)bh * TT) + (size_t)qtile * 64) * DD;
#pragma unroll
    for (int i = tid; i < 1024; i += 256) {
        int r = i >> 4, k4 = (i & 15) << 2;
        float4 q4 = ((const float4*)qb)[i];
        q4.x *= 0.125f; q4.y *= 0.125f; q4.z *= 0.125f; q4.w *= 0.125f;
        *(float4*)(Qs + r * KSTR + k4) = q4;
    }

    float m[4], l[4], O[4][4];
#pragma unroll
    for (int i = 0; i < 4; ++i) {
        m[i] = -1e30f; l[i] = 0.f;
#pragma unroll
        for (int j = 0; j < 4; ++j) O[i][j] = 0.f;
    }

    for (int t0 = 0; t0 <= qtile; ++t0) {
        __syncthreads();
        const float* kb = kn + (((size_t)bh * TT) + (size_t)t0 * 64) * DD;
        const float* vb = vv + (((size_t)bh * TT) + (size_t)t0 * 64) * DD;
#pragma unroll
        for (int i = tid; i < 1024; i += 256) {
            int r = i >> 4, k4 = (i & 15) << 2;
            *(float4*)(Ks + r * KSTR + k4) = ((const float4*)kb)[i];
            *(float4*)(Vs + r * KSTR + k4) = ((const float4*)vb)[i];
        }
        __syncthreads();

        float S[4][4];
#pragma unroll
        for (int i = 0; i < 4; ++i)
#pragma unroll
            for (int j = 0; j < 4; ++j) S[i][j] = 0.f;

#pragma unroll
        for (int k = 0; k < 64; k += 4) {
            float4 q4[4];
#pragma unroll
            for (int i = 0; i < 4; ++i)
                q4[i] = *(const float4*)(Qs + (ty * 4 + i) * KSTR + k);
#pragma unroll
            for (int j = 0; j < 4; ++j) {
                float4 kv = *(const float4*)(Ks + (tx + 16 * j) * KSTR + k);
#pragma unroll
                for (int i = 0; i < 4; ++i)
                    S[i][j] += q4[i].x * kv.x + q4[i].y * kv.y + q4[i].z * kv.z + q4[i].w * kv.w;
            }
        }

        bool diag = (t0 == qtile);
        int kv0 = t0 * 64;
        int qg0 = qtile * 64 + ty * 4;
#pragma unroll
        for (int i = 0; i < 4; ++i) {
            float rmx = -1e30f;
#pragma unroll
            for (int j = 0; j < 4; ++j) {
                if (diag && (kv0 + tx + 16 * j) > (qg0 + i)) S[i][j] = -1e30f;
                rmx = fmaxf(rmx, S[i][j]);
            }
#pragma unroll
            for (int off = 8; off; off >>= 1)
                rmx = fmaxf(rmx, __shfl_xor_sync(0xffffffffu, rmx, off, 16));
            float mnew  = fmaxf(m[i], rmx);
            float alpha = __expf(m[i] - mnew);
            float rs = 0.f;
#pragma unroll
            for (int j = 0; j < 4; ++j) {
                float p = __expf(S[i][j] - mnew);
                S[i][j] = p; rs += p;
            }
#pragma unroll
            for (int off = 8; off; off >>= 1)
                rs += __shfl_xor_sync(0xffffffffu, rs, off, 16);
            l[i] = l[i] * alpha + rs;
            m[i] = mnew;
#pragma unroll
            for (int j = 0; j < 4; ++j) O[i][j] *= alpha;
        }

        __syncthreads();
#pragma unroll
        for (int i = 0; i < 4; ++i)
#pragma unroll
            for (int j = 0; j < 4; ++j)
                Ks[(ty * 4 + i) * KSTR + tx + 16 * j] = S[i][j];
        __syncthreads();

#pragma unroll
        for (int k = 0; k < 64; k += 4) {
            float4 p4[4];
#pragma unroll
            for (int i = 0; i < 4; ++i)
                p4[i] = *(const float4*)(Ks + (ty * 4 + i) * KSTR + k);
#pragma unroll
            for (int kk = 0; kk < 4; ++kk) {
                float vr[4];
#pragma unroll
                for (int j = 0; j < 4; ++j)
                    vr[j] = Vs[(k + kk) * KSTR + tx + 16 * j];
#pragma unroll
                for (int i = 0; i < 4; ++i) {
                    float pv = (kk == 0) ? p4[i].x : (kk == 1) ? p4[i].y
                             : (kk == 2) ? p4[i].z : p4[i].w;
#pragma unroll
                    for (int j = 0; j < 4; ++j) O[i][j] += pv * vr[j];
                }
            }
        }
    }

    int b = bh >> 4, h = bh & 15;
#pragma unroll
    for (int i = 0; i < 4; ++i) {
        size_t tok = (size_t)b * TT + (size_t)qtile * 64 + ty * 4 + i;
        float invl = 1.0f / l[i];
#pragma unroll
        for (int j = 0; j < 4; ++j)
            attn[tok * CC + h * DD + tx + 16 * j] = O[i][j] * invl;
    }
}

// ---------------- launch ----------------
// Inputs identified by element count:
//   x 8388608, Wqkv 3145728, bqkv 3072, Wproj 1048576, bproj 1024, lamb 1 (identity)
extern "C" void kernel_launch(void* const* d_in, const int* in_sizes, int n_in,
                              void* d_out, int out_size)
{
    const float* x     = nullptr;
    const float* Wqkv  = nullptr;
    const float* bqkv  = nullptr;
    const float* Wproj = nullptr;
    const float* bproj = nullptr;

    for (int i = 0; i < n_in; ++i) {
        switch (in_sizes[i]) {
            case 8388608: x     = (const float*)d_in[i]; break;
            case 3145728: Wqkv  = (const float*)d_in[i]; break;
            case 3072:    bqkv  = (const float*)d_in[i]; break;
            case 1048576: Wproj = (const float*)d_in[i]; break;
            case 1024:    bproj = (const float*)d_in[i]; break;
            default: break; // lamb unused
        }
    }

    float* out = (float*)d_out;

    float *qkv, *qn, *kn, *vn, *attn;
    cudaGetSymbolAddress((void**)&qkv,  g_qkv);
    cudaGetSymbolAddress((void**)&qn,   g_qn);
    cudaGetSymbolAddress((void**)&kn,   g_kn);
    cudaGetSymbolAddress((void**)&vn,   g_vn);
    cudaGetSymbolAddress((void**)&attn, g_attn);

    // 1) QKV = x @ Wqkv + bqkv
    sgemm_bias_kernel<<<dim3(C3 / GBN, NTOK / GBM), 256>>>(x, Wqkv, bqkv, qkv, NTOK, C3, CC);

    // 2) rmsnorm + rope (standard sign) + head layout
    rmsrope_kernel<<<(BB * HH * TT) / 8, 256>>>(qkv, qn, kn, vn);

    // 3) causal flash attention
    cudaFuncSetAttribute(flash_kernel, cudaFuncAttributeMaxDynamicSharedMemorySize, FL_SMEM);
    flash_kernel<<<dim3(TT / 64, BB * HH), 256, FL_SMEM>>>(qn, kn, vn, attn);

    // 4) out = attn @ Wproj + bproj
    sgemm_bias_kernel<<<dim3(CC / GBN, NTOK / GBM), 256>>>(attn, Wproj, bproj, out, NTOK, CC, CC);

    // 5) value output if the buffer has room for the second tuple element
    if ((size_t)out_size >= 2 * OUT0_ELEMS) {
        size_t n4 = OUT0_ELEMS / 4;
        copy_kernel<<<(unsigned)((n4 + 255) / 256), 256>>>(vn, out + OUT0_ELEMS, n4);
    }
}

// round 10
// speedup vs baseline: 1.3018x; 1.3018x over previous
#include <cuda_runtime.h>
#include <cuda_bf16.h>
#include <math.h>
#include <stddef.h>
#include <stdint.h>

#define BB 4
#define TT 2048
#define CC 1024
#define HH 16
#define DD 64
#define NTOK (BB*TT)     /* 8192 */
#define C3   (3*CC)      /* 3072 */
#define OUT0_ELEMS ((size_t)BB*TT*CC)   /* 8388608 */

// ---------------- scratch (no allocations allowed) ----------------
__device__ float g_qkv [(size_t)NTOK * C3];
__device__ float g_qn  [(size_t)BB*HH*TT*DD];
__device__ float g_kn  [(size_t)BB*HH*TT*DD];
__device__ float g_vn  [(size_t)BB*HH*TT*DD];
__device__ float g_attn[(size_t)NTOK * CC];
// bf16 split operands
__device__ __nv_bfloat16 g_xhi[(size_t)NTOK*CC];
__device__ __nv_bfloat16 g_xlo[(size_t)NTOK*CC];
__device__ __nv_bfloat16 g_wqT_hi[(size_t)C3*CC];   // Wqkv^T [3072][1024]
__device__ __nv_bfloat16 g_wqT_lo[(size_t)C3*CC];
__device__ __nv_bfloat16 g_wpT_hi[(size_t)CC*CC];   // Wproj^T [1024][1024]
__device__ __nv_bfloat16 g_wpT_lo[(size_t)CC*CC];
__device__ __nv_bfloat16 g_ahi[(size_t)NTOK*CC];
__device__ __nv_bfloat16 g_alo[(size_t)NTOK*CC];

// ================= helpers =================
__device__ __forceinline__ uint32_t smem_u32(const void* p) {
    uint32_t a;
    asm("{ .reg .u64 t; cvta.to.shared.u64 t, %1; cvt.u32.u64 %0, t; }" : "=r"(a) : "l"(p));
    return a;
}

__device__ __forceinline__ void ldsm_x4(uint32_t& a0, uint32_t& a1, uint32_t& a2, uint32_t& a3, uint32_t addr) {
    asm volatile("ldmatrix.sync.aligned.m8n8.x4.shared.b16 {%0,%1,%2,%3}, [%4];"
                 : "=r"(a0), "=r"(a1), "=r"(a2), "=r"(a3) : "r"(addr));
}
__device__ __forceinline__ void ldsm_x2(uint32_t& b0, uint32_t& b1, uint32_t addr) {
    asm volatile("ldmatrix.sync.aligned.m8n8.x2.shared.b16 {%0,%1}, [%2];"
                 : "=r"(b0), "=r"(b1) : "r"(addr));
}
__device__ __forceinline__ void mma_bf16(float* c, const uint32_t* a, const uint32_t* b) {
    asm volatile("mma.sync.aligned.m16n8k16.row.col.f32.bf16.bf16.f32 "
                 "{%0,%1,%2,%3}, {%4,%5,%6,%7}, {%8,%9}, {%0,%1,%2,%3};"
                 : "+f"(c[0]), "+f"(c[1]), "+f"(c[2]), "+f"(c[3])
                 : "r"(a[0]), "r"(a[1]), "r"(a[2]), "r"(a[3]), "r"(b[0]), "r"(b[1]));
}

// ================= mma.sync GEMM: C = A @ B^T + bias =================
// A: [M][K] bf16 (hi/lo), B: [N][K] bf16 (hi/lo, pre-transposed weights).
// CTA tile 128x128, 8 warps (2m x 4n), warp tile 64x32, K chunk 32.
// smem rows padded to 80B (40 halves) -> conflict-free ldmatrix.
#define ROWB 80
#define BUFB (128 * ROWB)   /* 10240 */

__global__ __launch_bounds__(256) void mma_gemm_kernel(
    const __nv_bfloat16* __restrict__ Ahi, const __nv_bfloat16* __restrict__ Alo,
    const __nv_bfloat16* __restrict__ Bhi, const __nv_bfloat16* __restrict__ Blo,
    const float* __restrict__ bias, float* __restrict__ C,
    int M, int N, int K)
{
    __shared__ __align__(16) char smem[4 * BUFB];   // 40960 B
    char* sAhi = smem;
    char* sAlo = smem + BUFB;
    char* sBhi = smem + 2 * BUFB;
    char* sBlo = smem + 3 * BUFB;

    const int tid = threadIdx.x;
    const int wid = tid >> 5, lane = tid & 31;
    const int wm = wid & 1, wn = wid >> 1;          // 2 x 4 warps
    const int m0 = blockIdx.y * 128, n0 = blockIdx.x * 128;

    const uint32_t uAhi = smem_u32(sAhi), uAlo = smem_u32(sAlo);
    const uint32_t uBhi = smem_u32(sBhi), uBlo = smem_u32(sBlo);

    float acc[4][4][4];
#pragma unroll
    for (int i = 0; i < 4; ++i)
#pragma unroll
        for (int j = 0; j < 4; ++j)
#pragma unroll
            for (int r = 0; r < 4; ++r) acc[i][j][r] = 0.f;

    // ldmatrix source addresses (within-buffer offsets), per lane
    // A frag (m16xk16): rows mt*16 + (lane&15), col bytes kh*32 + ((lane>>4)&1)*16
    const uint32_t aRow = (uint32_t)(lane & 15);
    const uint32_t aColSel = (uint32_t)(((lane >> 4) & 1) * 16);
    // B frag (n8xk16): rows nt*8 + (lane&7), col bytes kh*32 + ((lane>>3)&1)*16
    const uint32_t bRow = (uint32_t)(lane & 7);
    const uint32_t bColSel = (uint32_t)(((lane >> 3) & 1) * 16);

    for (int k0 = 0; k0 < K; k0 += 32) {
        // ---- gmem -> smem: 128 rows x 32 halves per buffer ----
        const __nv_bfloat16* pa_hi = Ahi + (size_t)m0 * K + k0;
        const __nv_bfloat16* pa_lo = Alo + (size_t)m0 * K + k0;
        const __nv_bfloat16* pb_hi = Bhi + (size_t)n0 * K + k0;
        const __nv_bfloat16* pb_lo = Blo + (size_t)n0 * K + k0;
#pragma unroll
        for (int it = 0; it < 2; ++it) {
            int id = tid + it * 256;                // 0..511
            int row = id >> 2, seg = id & 3;        // seg: 16B units
            size_t go = (size_t)row * K + seg * 8;
            int so = row * ROWB + seg * 16;
            *(uint4*)(sAhi + so) = *(const uint4*)(pa_hi + go);
            *(uint4*)(sAlo + so) = *(const uint4*)(pa_lo + go);
            *(uint4*)(sBhi + so) = *(const uint4*)(pb_hi + go);
            *(uint4*)(sBlo + so) = *(const uint4*)(pb_lo + go);
        }
        __syncthreads();

#pragma unroll
        for (int kh = 0; kh < 2; ++kh) {
            uint32_t ahi[4][4], alo[4][4], bhi[4][2], blo[4][2];
#pragma unroll
            for (int mt = 0; mt < 4; ++mt) {
                uint32_t off = (uint32_t)((wm * 64 + mt * 16 + aRow) * ROWB) + kh * 32 + aColSel;
                ldsm_x4(ahi[mt][0], ahi[mt][1], ahi[mt][2], ahi[mt][3], uAhi + off);
                ldsm_x4(alo[mt][0], alo[mt][1], alo[mt][2], alo[mt][3], uAlo + off);
            }
#pragma unroll
            for (int nt = 0; nt < 4; ++nt) {
                uint32_t off = (uint32_t)((wn * 32 + nt * 8 + bRow) * ROWB) + kh * 32 + bColSel;
                ldsm_x2(bhi[nt][0], bhi[nt][1], uBhi + off);
                ldsm_x2(blo[nt][0], blo[nt][1], uBlo + off);
            }
#pragma unroll
            for (int mt = 0; mt < 4; ++mt)
#pragma unroll
                for (int nt = 0; nt < 4; ++nt) {
                    mma_bf16(acc[mt][nt], ahi[mt], bhi[nt]);
                    mma_bf16(acc[mt][nt], ahi[mt], blo[nt]);
                    mma_bf16(acc[mt][nt], alo[mt], bhi[nt]);
                }
        }
        __syncthreads();
    }

    // ---- epilogue: acc regs c0,c1 -> (row, col..col+1), c2,c3 -> (row+8) ----
    const int rbase = m0 + wm * 64 + (lane >> 2);
    const int cbase = n0 + wn * 32 + (lane & 3) * 2;
#pragma unroll
    for (int mt = 0; mt < 4; ++mt)
#pragma unroll
        for (int nt = 0; nt < 4; ++nt) {
            int r = rbase + mt * 16;
            int c = cbase + nt * 8;
            float2 bv = *(const float2*)(bias + c);
            float2 o0 = { acc[mt][nt][0] + bv.x, acc[mt][nt][1] + bv.y };
            float2 o1 = { acc[mt][nt][2] + bv.x, acc[mt][nt][3] + bv.y };
            *(float2*)(C + (size_t)r * N + c) = o0;
            *(float2*)(C + (size_t)(r + 8) * N + c) = o1;
        }
}

// ================= split fp32 -> (hi, lo) bf16 =================
__global__ __launch_bounds__(256) void split_kernel(
    const float* __restrict__ src, __nv_bfloat16* __restrict__ hi,
    __nv_bfloat16* __restrict__ lo, size_t n4)
{
    size_t i = (size_t)blockIdx.x * blockDim.x + threadIdx.x;
    if (i >= n4) return;
    float4 v = ((const float4*)src)[i];
    __nv_bfloat16 h0 = __float2bfloat16(v.x), h1 = __float2bfloat16(v.y);
    __nv_bfloat16 h2 = __float2bfloat16(v.z), h3 = __float2bfloat16(v.w);
    __nv_bfloat16 l0 = __float2bfloat16(v.x - __bfloat162float(h0));
    __nv_bfloat16 l1 = __float2bfloat16(v.y - __bfloat162float(h1));
    __nv_bfloat16 l2 = __float2bfloat16(v.z - __bfloat162float(h2));
    __nv_bfloat16 l3 = __float2bfloat16(v.w - __bfloat162float(h3));
    ((__nv_bfloat162*)hi)[2 * i]     = __nv_bfloat162(h0, h1);
    ((__nv_bfloat162*)hi)[2 * i + 1] = __nv_bfloat162(h2, h3);
    ((__nv_bfloat162*)lo)[2 * i]     = __nv_bfloat162(l0, l1);
    ((__nv_bfloat162*)lo)[2 * i + 1] = __nv_bfloat162(l2, l3);
}

// ================= transpose + split: W[K][N] fp32 -> hi/lo [N][K] bf16 =================
__global__ __launch_bounds__(256) void transpose_split_kernel(
    const float* __restrict__ W, __nv_bfloat16* __restrict__ hi,
    __nv_bfloat16* __restrict__ lo, int K, int N)
{
    __shared__ float t[32][33];
    int tx = threadIdx.x, ty = threadIdx.y;
    int n0 = blockIdx.x * 32, k0 = blockIdx.y * 32;
#pragma unroll
    for (int i = 0; i < 4; ++i)
        t[ty + i * 8][tx] = W[(size_t)(k0 + ty + i * 8) * N + n0 + tx];
    __syncthreads();
#pragma unroll
    for (int i = 0; i < 4; ++i) {
        int n = n0 + ty + i * 8, k = k0 + tx;
        float v = t[tx][ty + i * 8];
        __nv_bfloat16 h = __float2bfloat16(v);
        hi[(size_t)n * K + k] = h;
        lo[(size_t)n * K + k] = __float2bfloat16(v - __bfloat162float(h));
    }
}

// ================= RMSNorm + RoPE (standard sign) =================
__global__ __launch_bounds__(256) void rmsrope_kernel(
    const float* __restrict__ qkv,
    float* __restrict__ qn, float* __restrict__ kn, float* __restrict__ vout)
{
    int gw   = (int)((blockIdx.x * blockDim.x + threadIdx.x) >> 5);
    int lane = threadIdx.x & 31;
    if (gw >= BB * HH * TT) return;
    int t = gw % TT;
    int h = (gw / TT) % HH;
    int b = gw / (TT * HH);

    size_t tok = (size_t)b * TT + t;
    const float* base = qkv + tok * C3 + h * DD;
    size_t oidx = ((size_t)(b * HH + h) * TT + t) * DD;

    float ex  = (float)lane * (1.0f / 32.0f);
    float inv = expf(-ex * 9.210340371976184f);
    float ang = (float)t * inv;
    float cs, sn;
    sincosf(ang, &cs, &sn);

    {
        float x1 = base[lane], x2 = base[lane + 32];
        float ss = x1 * x1 + x2 * x2;
#pragma unroll
        for (int off = 16; off; off >>= 1) ss += __shfl_xor_sync(0xffffffffu, ss, off);
        float r = rsqrtf(ss * (1.0f / 64.0f) + 1e-6f);
        x1 *= r; x2 *= r;
        qn[oidx + lane]      = x1 * cs - x2 * sn;
        qn[oidx + lane + 32] = x1 * sn + x2 * cs;
    }
    {
        const float* kb = base + CC;
        float x1 = kb[lane], x2 = kb[lane + 32];
        float ss = x1 * x1 + x2 * x2;
#pragma unroll
        for (int off = 16; off; off >>= 1) ss += __shfl_xor_sync(0xffffffffu, ss, off);
        float r = rsqrtf(ss * (1.0f / 64.0f) + 1e-6f);
        x1 *= r; x2 *= r;
        kn[oidx + lane]      = x1 * cs - x2 * sn;
        kn[oidx + lane + 32] = x1 * sn + x2 * cs;
    }
    vout[oidx + lane]      = base[2 * CC + lane];
    vout[oidx + lane + 32] = base[2 * CC + lane + 32];
}

// ---------------- value copy ----------------
__global__ __launch_bounds__(256) void copy_kernel(
    const float* __restrict__ src, float* __restrict__ dst, size_t n4)
{
    size_t i = (size_t)blockIdx.x * blockDim.x + threadIdx.x;
    if (i < n4) ((float4*)dst)[i] = ((const float4*)src)[i];
}

// ---------------- flash attention, fp32, 64x64 tiles ----------------
#define KSTR 68
#define FL_SMEM (3 * 64 * KSTR * 4)

__global__ __launch_bounds__(256) void flash_kernel(
    const float* __restrict__ qn, const float* __restrict__ kn,
    const float* __restrict__ vv, float* __restrict__ attn)
{
    extern __shared__ float sm[];
    float* Qs = sm;
    float* Ks = sm + 64 * KSTR;
    float* Vs = sm + 2 * 64 * KSTR;

    int qtile = blockIdx.x;
    int bh    = blockIdx.y;
    int tid = threadIdx.x;
    int tx = tid & 15, ty = tid >> 4;

    const float* qb = qn + (((size_t)bh * TT) + (size_t)qtile * 64) * DD;
#pragma unroll
    for (int i = tid; i < 1024; i += 256) {
        int r = i >> 4, k4 = (i & 15) << 2;
        float4 q4 = ((const float4*)qb)[i];
        q4.x *= 0.125f; q4.y *= 0.125f; q4.z *= 0.125f; q4.w *= 0.125f;
        *(float4*)(Qs + r * KSTR + k4) = q4;
    }

    float m[4], l[4], O[4][4];
#pragma unroll
    for (int i = 0; i < 4; ++i) {
        m[i] = -1e30f; l[i] = 0.f;
#pragma unroll
        for (int j = 0; j < 4; ++j) O[i][j] = 0.f;
    }

    for (int t0 = 0; t0 <= qtile; ++t0) {
        __syncthreads();
        const float* kb = kn + (((size_t)bh * TT) + (size_t)t0 * 64) * DD;
        const float* vb = vv + (((size_t)bh * TT) + (size_t)t0 * 64) * DD;
#pragma unroll
        for (int i = tid; i < 1024; i += 256) {
            int r = i >> 4, k4 = (i & 15) << 2;
            *(float4*)(Ks + r * KSTR + k4) = ((const float4*)kb)[i];
            *(float4*)(Vs + r * KSTR + k4) = ((const float4*)vb)[i];
        }
        __syncthreads();

        float S[4][4];
#pragma unroll
        for (int i = 0; i < 4; ++i)
#pragma unroll
            for (int j = 0; j < 4; ++j) S[i][j] = 0.f;

#pragma unroll
        for (int k = 0; k < 64; k += 4) {
            float4 q4[4];
#pragma unroll
            for (int i = 0; i < 4; ++i)
                q4[i] = *(const float4*)(Qs + (ty * 4 + i) * KSTR + k);
#pragma unroll
            for (int j = 0; j < 4; ++j) {
                float4 kv = *(const float4*)(Ks + (tx + 16 * j) * KSTR + k);
#pragma unroll
                for (int i = 0; i < 4; ++i)
                    S[i][j] += q4[i].x * kv.x + q4[i].y * kv.y + q4[i].z * kv.z + q4[i].w * kv.w;
            }
        }

        bool diag = (t0 == qtile);
        int kv0 = t0 * 64;
        int qg0 = qtile * 64 + ty * 4;
#pragma unroll
        for (int i = 0; i < 4; ++i) {
            float rmx = -1e30f;
#pragma unroll
            for (int j = 0; j < 4; ++j) {
                if (diag && (kv0 + tx + 16 * j) > (qg0 + i)) S[i][j] = -1e30f;
                rmx = fmaxf(rmx, S[i][j]);
            }
#pragma unroll
            for (int off = 8; off; off >>= 1)
                rmx = fmaxf(rmx, __shfl_xor_sync(0xffffffffu, rmx, off, 16));
            float mnew  = fmaxf(m[i], rmx);
            float alpha = __expf(m[i] - mnew);
            float rs = 0.f;
#pragma unroll
            for (int j = 0; j < 4; ++j) {
                float p = __expf(S[i][j] - mnew);
                S[i][j] = p; rs += p;
            }
#pragma unroll
            for (int off = 8; off; off >>= 1)
                rs += __shfl_xor_sync(0xffffffffu, rs, off, 16);
            l[i] = l[i] * alpha + rs;
            m[i] = mnew;
#pragma unroll
            for (int j = 0; j < 4; ++j) O[i][j] *= alpha;
        }

        __syncthreads();
#pragma unroll
        for (int i = 0; i < 4; ++i)
#pragma unroll
            for (int j = 0; j < 4; ++j)
                Ks[(ty * 4 + i) * KSTR + tx + 16 * j] = S[i][j];
        __syncthreads();

#pragma unroll
        for (int k = 0; k < 64; k += 4) {
            float4 p4[4];
#pragma unroll
            for (int i = 0; i < 4; ++i)
                p4[i] = *(const float4*)(Ks + (ty * 4 + i) * KSTR + k);
#pragma unroll
            for (int kk = 0; kk < 4; ++kk) {
                float vr[4];
#pragma unroll
                for (int j = 0; j < 4; ++j)
                    vr[j] = Vs[(k + kk) * KSTR + tx + 16 * j];
#pragma unroll
                for (int i = 0; i < 4; ++i) {
                    float pv = (kk == 0) ? p4[i].x : (kk == 1) ? p4[i].y
                             : (kk == 2) ? p4[i].z : p4[i].w;
#pragma unroll
                    for (int j = 0; j < 4; ++j) O[i][j] += pv * vr[j];
                }
            }
        }
    }

    int b = bh >> 4, h = bh & 15;
#pragma unroll
    for (int i = 0; i < 4; ++i) {
        size_t tok = (size_t)b * TT + (size_t)qtile * 64 + ty * 4 + i;
        float invl = 1.0f / l[i];
#pragma unroll
        for (int j = 0; j < 4; ++j)
            attn[tok * CC + h * DD + tx + 16 * j] = O[i][j] * invl;
    }
}

// ================= launch =================
extern "C" void kernel_launch(void* const* d_in, const int* in_sizes, int n_in,
                              void* d_out, int out_size)
{
    const float* x = nullptr; const float* Wqkv = nullptr; const float* bqkv = nullptr;
    const float* Wproj = nullptr; const float* bproj = nullptr;
    for (int i = 0; i < n_in; ++i) {
        switch (in_sizes[i]) {
            case 8388608: x     = (const float*)d_in[i]; break;
            case 3145728: Wqkv  = (const float*)d_in[i]; break;
            case 3072:    bqkv  = (const float*)d_in[i]; break;
            case 1048576: Wproj = (const float*)d_in[i]; break;
            case 1024:    bproj = (const float*)d_in[i]; break;
            default: break; // lamb: exact identity, unused
        }
    }

    float* out = (float*)d_out;

    float *qkv, *qn, *kn, *vn, *attn;
    __nv_bfloat16 *xhi, *xlo, *wqhi, *wqlo, *wphi, *wplo, *ahi, *alo;
    cudaGetSymbolAddress((void**)&qkv, g_qkv);
    cudaGetSymbolAddress((void**)&qn,  g_qn);
    cudaGetSymbolAddress((void**)&kn,  g_kn);
    cudaGetSymbolAddress((void**)&vn,  g_vn);
    cudaGetSymbolAddress((void**)&attn, g_attn);
    cudaGetSymbolAddress((void**)&xhi, g_xhi);
    cudaGetSymbolAddress((void**)&xlo, g_xlo);
    cudaGetSymbolAddress((void**)&wqhi, g_wqT_hi);
    cudaGetSymbolAddress((void**)&wqlo, g_wqT_lo);
    cudaGetSymbolAddress((void**)&wphi, g_wpT_hi);
    cudaGetSymbolAddress((void**)&wplo, g_wpT_lo);
    cudaGetSymbolAddress((void**)&ahi, g_ahi);
    cudaGetSymbolAddress((void**)&alo, g_alo);

    cudaFuncSetAttribute(flash_kernel, cudaFuncAttributeMaxDynamicSharedMemorySize, FL_SMEM);

    // 0) operand prep
    {
        size_t n4 = ((size_t)NTOK * CC) / 4;
        split_kernel<<<(unsigned)((n4 + 255) / 256), 256>>>(x, xhi, xlo, n4);
    }
    transpose_split_kernel<<<dim3(C3 / 32, CC / 32), dim3(32, 8)>>>(Wqkv, wqhi, wqlo, CC, C3);
    transpose_split_kernel<<<dim3(CC / 32, CC / 32), dim3(32, 8)>>>(Wproj, wphi, wplo, CC, CC);

    // 1) QKV = x @ Wqkv + bqkv  (mma.sync tensor cores, split-bf16)
    mma_gemm_kernel<<<dim3(C3 / 128, NTOK / 128), 256>>>(
        xhi, xlo, wqhi, wqlo, bqkv, qkv, NTOK, C3, CC);

    // 2) rmsnorm + rope + head layout
    rmsrope_kernel<<<(BB * HH * TT) / 8, 256>>>(qkv, qn, kn, vn);

    // 3) causal flash attention (fp32)
    flash_kernel<<<dim3(TT / 64, BB * HH), 256, FL_SMEM>>>(qn, kn, vn, attn);

    // 4) split attn, then out = attn @ Wproj + bproj
    {
        size_t n4 = ((size_t)NTOK * CC) / 4;
        split_kernel<<<(unsigned)((n4 + 255) / 256), 256>>>(attn, ahi, alo, n4);
    }
    mma_gemm_kernel<<<dim3(CC / 128, NTOK / 128), 256>>>(
        ahi, alo, wphi, wplo, bproj, out, NTOK, CC, CC);

    // 5) value output
    if ((size_t)out_size >= 2 * OUT0_ELEMS) {
        size_t n4 = OUT0_ELEMS / 4;
        copy_kernel<<<(unsigned)((n4 + 255) / 256), 256>>>(vn, out + OUT0_ELEMS, n4);
    }
}

// round 11
// speedup vs baseline: 2.2952x; 1.7631x over previous
#include <cuda_runtime.h>
#include <cuda_bf16.h>
#include <math.h>
#include <stddef.h>
#include <stdint.h>

#define BB 4
#define TT 2048
#define CC 1024
#define HH 16
#define DD 64
#define BH (BB*HH)
#define NTOK (BB*TT)     /* 8192 */
#define C3   (3*CC)      /* 3072 */
#define OUT0_ELEMS ((size_t)BB*TT*CC)   /* 8388608 */

// ---------------- scratch ----------------
__device__ float g_qkv [(size_t)NTOK * C3];
__device__ float g_vn  [(size_t)BH*TT*DD];          // fp32 V (value output)
__device__ float g_attn[(size_t)NTOK * CC];
// bf16 split operands
__device__ __nv_bfloat16 g_xhi[(size_t)NTOK*CC];
__device__ __nv_bfloat16 g_xlo[(size_t)NTOK*CC];
__device__ __nv_bfloat16 g_wqT_hi[(size_t)C3*CC];
__device__ __nv_bfloat16 g_wqT_lo[(size_t)C3*CC];
__device__ __nv_bfloat16 g_wpT_hi[(size_t)CC*CC];
__device__ __nv_bfloat16 g_wpT_lo[(size_t)CC*CC];
__device__ __nv_bfloat16 g_ahi[(size_t)NTOK*CC];
__device__ __nv_bfloat16 g_alo[(size_t)NTOK*CC];
// flash operands (head-major [bh][t][d]); q pre-scaled by 1/8
__device__ __nv_bfloat16 g_qh[(size_t)BH*TT*DD];
__device__ __nv_bfloat16 g_ql[(size_t)BH*TT*DD];
__device__ __nv_bfloat16 g_kh[(size_t)BH*TT*DD];
__device__ __nv_bfloat16 g_kl[(size_t)BH*TT*DD];
__device__ __nv_bfloat16 g_vh[(size_t)BH*TT*DD];
__device__ __nv_bfloat16 g_vl[(size_t)BH*TT*DD];

// ================= helpers =================
__device__ __forceinline__ uint32_t smem_u32(const void* p) {
    uint32_t a;
    asm("{ .reg .u64 t; cvta.to.shared.u64 t, %1; cvt.u32.u64 %0, t; }" : "=r"(a) : "l"(p));
    return a;
}
__device__ __forceinline__ void ldsm_x4(uint32_t& a0, uint32_t& a1, uint32_t& a2, uint32_t& a3, uint32_t addr) {
    asm volatile("ldmatrix.sync.aligned.m8n8.x4.shared.b16 {%0,%1,%2,%3}, [%4];"
                 : "=r"(a0), "=r"(a1), "=r"(a2), "=r"(a3) : "r"(addr));
}
__device__ __forceinline__ void ldsm_x2(uint32_t& b0, uint32_t& b1, uint32_t addr) {
    asm volatile("ldmatrix.sync.aligned.m8n8.x2.shared.b16 {%0,%1}, [%2];"
                 : "=r"(b0), "=r"(b1) : "r"(addr));
}
__device__ __forceinline__ void ldsm_x2t(uint32_t& b0, uint32_t& b1, uint32_t addr) {
    asm volatile("ldmatrix.sync.aligned.m8n8.x2.trans.shared.b16 {%0,%1}, [%2];"
                 : "=r"(b0), "=r"(b1) : "r"(addr));
}
__device__ __forceinline__ void mma_bf16(float* c, const uint32_t* a, const uint32_t* b) {
    asm volatile("mma.sync.aligned.m16n8k16.row.col.f32.bf16.bf16.f32 "
                 "{%0,%1,%2,%3}, {%4,%5,%6,%7}, {%8,%9}, {%0,%1,%2,%3};"
                 : "+f"(c[0]), "+f"(c[1]), "+f"(c[2]), "+f"(c[3])
                 : "r"(a[0]), "r"(a[1]), "r"(a[2]), "r"(a[3]), "r"(b[0]), "r"(b[1]));
}
#define CPASYNC16(dst, src) asm volatile("cp.async.cg.shared.global [%0], [%1], 16;" :: "r"(dst), "l"(src))
#define CPCOMMIT()          asm volatile("cp.async.commit_group;" ::: "memory")
#define CPWAIT(n)           asm volatile("cp.async.wait_group %0;" :: "n"(n) : "memory")

__device__ __forceinline__ uint32_t pack2(float x, float y) {
    __nv_bfloat162 t = __nv_bfloat162(__float2bfloat16(x), __float2bfloat16(y));
    return *(uint32_t*)&t;
}

// ================= cp.async double-buffered mma GEMM: C = A @ B^T + bias =================
#define ROWB 80
#define BUFB (128 * ROWB)     /* 10240 */
#define STAGE (4 * BUFB)      /* 40960 */
#define GEMM_SMEM (2 * STAGE) /* 81920 */

__global__ __launch_bounds__(256) void mma_gemm_kernel(
    const __nv_bfloat16* __restrict__ Ahi, const __nv_bfloat16* __restrict__ Alo,
    const __nv_bfloat16* __restrict__ Bhi, const __nv_bfloat16* __restrict__ Blo,
    const float* __restrict__ bias, float* __restrict__ C,
    int M, int N, int K)
{
    extern __shared__ __align__(16) char dsm[];
    const int tid = threadIdx.x;
    const int wid = tid >> 5, lane = tid & 31;
    const int wm = wid & 1, wn = wid >> 1;
    const int m0 = blockIdx.y * 128, n0 = blockIdx.x * 128;
    const uint32_t ubase = smem_u32(dsm);

    float acc[4][4][4];
#pragma unroll
    for (int i = 0; i < 4; ++i)
#pragma unroll
        for (int j = 0; j < 4; ++j)
#pragma unroll
            for (int r = 0; r < 4; ++r) acc[i][j][r] = 0.f;

    const uint32_t aRow = (uint32_t)(lane & 15);
    const uint32_t aColSel = (uint32_t)(((lane >> 4) & 1) * 16);
    const uint32_t bRow = (uint32_t)(lane & 7);
    const uint32_t bColSel = (uint32_t)(((lane >> 3) & 1) * 16);

    const int id0 = tid, id1 = tid + 256;
    const int r0i = id0 >> 2, s0i = id0 & 3, r1i = id1 >> 2, s1i = id1 & 3;

    // async issue of one k-chunk into stage sel
    auto issue = [&](int kt, int sel) {
        const __nv_bfloat16* pa_hi = Ahi + (size_t)m0 * K + kt * 32;
        const __nv_bfloat16* pa_lo = Alo + (size_t)m0 * K + kt * 32;
        const __nv_bfloat16* pb_hi = Bhi + (size_t)n0 * K + kt * 32;
        const __nv_bfloat16* pb_lo = Blo + (size_t)n0 * K + kt * 32;
        uint32_t sb = ubase + sel * STAGE;
        {
            size_t go = (size_t)r0i * K + s0i * 8;
            uint32_t so = (uint32_t)(r0i * ROWB + s0i * 16);
            CPASYNC16(sb + so,            (const char*)(pa_hi + go));
            CPASYNC16(sb + BUFB + so,     (const char*)(pa_lo + go));
            CPASYNC16(sb + 2*BUFB + so,   (const char*)(pb_hi + go));
            CPASYNC16(sb + 3*BUFB + so,   (const char*)(pb_lo + go));
        }
        {
            size_t go = (size_t)r1i * K + s1i * 8;
            uint32_t so = (uint32_t)(r1i * ROWB + s1i * 16);
            CPASYNC16(sb + so,            (const char*)(pa_hi + go));
            CPASYNC16(sb + BUFB + so,     (const char*)(pa_lo + go));
            CPASYNC16(sb + 2*BUFB + so,   (const char*)(pb_hi + go));
            CPASYNC16(sb + 3*BUFB + so,   (const char*)(pb_lo + go));
        }
    };

    const int KT = K / 32;
    issue(0, 0);
    CPCOMMIT();

    for (int kt = 0; kt < KT; ++kt) {
        if (kt + 1 < KT) { issue(kt + 1, (kt + 1) & 1); CPCOMMIT(); CPWAIT(1); }
        else             { CPWAIT(0); }
        __syncthreads();

        uint32_t sb = ubase + (kt & 1) * STAGE;
        uint32_t uAhi = sb, uAlo = sb + BUFB, uBhi = sb + 2*BUFB, uBlo = sb + 3*BUFB;
#pragma unroll
        for (int kh = 0; kh < 2; ++kh) {
            uint32_t ahi[4][4], alo[4][4], bhi[4][2], blo[4][2];
#pragma unroll
            for (int mt = 0; mt < 4; ++mt) {
                uint32_t off = (uint32_t)((wm * 64 + mt * 16 + aRow) * ROWB) + kh * 32 + aColSel;
                ldsm_x4(ahi[mt][0], ahi[mt][1], ahi[mt][2], ahi[mt][3], uAhi + off);
                ldsm_x4(alo[mt][0], alo[mt][1], alo[mt][2], alo[mt][3], uAlo + off);
            }
#pragma unroll
            for (int nt = 0; nt < 4; ++nt) {
                uint32_t off = (uint32_t)((wn * 32 + nt * 8 + bRow) * ROWB) + kh * 32 + bColSel;
                ldsm_x2(bhi[nt][0], bhi[nt][1], uBhi + off);
                ldsm_x2(blo[nt][0], blo[nt][1], uBlo + off);
            }
#pragma unroll
            for (int mt = 0; mt < 4; ++mt)
#pragma unroll
                for (int nt = 0; nt < 4; ++nt) {
                    mma_bf16(acc[mt][nt], ahi[mt], bhi[nt]);
                    mma_bf16(acc[mt][nt], ahi[mt], blo[nt]);
                    mma_bf16(acc[mt][nt], alo[mt], bhi[nt]);
                }
        }
        __syncthreads();
    }

    const int rbase = m0 + wm * 64 + (lane >> 2);
    const int cbase = n0 + wn * 32 + (lane & 3) * 2;
#pragma unroll
    for (int mt = 0; mt < 4; ++mt)
#pragma unroll
        for (int nt = 0; nt < 4; ++nt) {
            int r = rbase + mt * 16;
            int c = cbase + nt * 8;
            float2 bv = *(const float2*)(bias + c);
            float2 o0 = { acc[mt][nt][0] + bv.x, acc[mt][nt][1] + bv.y };
            float2 o1 = { acc[mt][nt][2] + bv.x, acc[mt][nt][3] + bv.y };
            *(float2*)(C + (size_t)r * N + c) = o0;
            *(float2*)(C + (size_t)(r + 8) * N + c) = o1;
        }
}

// ================= tensor-core flash attention =================
// CTA: 128 q rows (qt), 8 warps x m16. kv steps of 64. split-bf16 QK^T and PV.
#define FROW 72
#define FROWB 144
#define FBUF (64 * FROWB)   /* 9216 */

__global__ __launch_bounds__(256) void flash_tc_kernel(
    const __nv_bfloat16* __restrict__ qh, const __nv_bfloat16* __restrict__ ql,
    const __nv_bfloat16* __restrict__ kh, const __nv_bfloat16* __restrict__ kl,
    const __nv_bfloat16* __restrict__ vh, const __nv_bfloat16* __restrict__ vl,
    float* __restrict__ attn)
{
    __shared__ __align__(16) char sm[4 * FBUF];     // 36864 B
    char* sKhi = sm;  char* sKlo = sm + FBUF;
    char* sVhi = sm + 2 * FBUF; char* sVlo = sm + 3 * FBUF;
    const uint32_t uKhi = smem_u32(sKhi), uKlo = smem_u32(sKlo);
    const uint32_t uVhi = smem_u32(sVhi), uVlo = smem_u32(sVlo);

    const int qt = blockIdx.x;        // 0..15
    const int bh = blockIdx.y;        // 0..63
    const int tid = threadIdx.x;
    const int wid = tid >> 5, lane = tid & 31;
    const int Q0 = qt * 128;
    const int rowbase = Q0 + wid * 16;

    // ---- stage Q (hi rows0-63 -> sKhi, rows64-127 -> sVhi; lo likewise) ----
    {
        const __nv_bfloat16* qbh = qh + ((size_t)bh * TT + Q0) * DD;
        const __nv_bfloat16* qbl = ql + ((size_t)bh * TT + Q0) * DD;
#pragma unroll
        for (int it = 0; it < 4; ++it) {
            int id = tid + it * 256;              // 0..1023
            int row = id >> 3, seg = id & 7;
            size_t go = (size_t)row * DD + seg * 8;
            int drow = row & 63;
            char* dh = (row < 64) ? sKhi : sVhi;
            char* dl = (row < 64) ? sKlo : sVlo;
            *(uint4*)(dh + drow * FROWB + seg * 16) = *(const uint4*)(qbh + go);
            *(uint4*)(dl + drow * FROWB + seg * 16) = *(const uint4*)(qbl + go);
        }
    }
    __syncthreads();

    // Q fragments (persist in regs)
    uint32_t qfh[4][4], qfl[4][4];
    {
        uint32_t bufh = (wid < 4) ? uKhi : uVhi;
        uint32_t bufl = (wid < 4) ? uKlo : uVlo;
        uint32_t rsel = (uint32_t)(((wid & 3) * 16 + (lane & 15)) * FROWB);
        uint32_t csel = (uint32_t)(((lane >> 4) & 1) * 16);
#pragma unroll
        for (int kc = 0; kc < 4; ++kc) {
            uint32_t off = rsel + kc * 32 + csel;
            ldsm_x4(qfh[kc][0], qfh[kc][1], qfh[kc][2], qfh[kc][3], bufh + off);
            ldsm_x4(qfl[kc][0], qfl[kc][1], qfl[kc][2], qfl[kc][3], bufl + off);
        }
    }
    __syncthreads();

    float mrow0 = -1e30f, mrow1 = -1e30f, lrow0 = 0.f, lrow1 = 0.f;
    float O[8][4];
#pragma unroll
    for (int nt = 0; nt < 8; ++nt)
#pragma unroll
        for (int j = 0; j < 4; ++j) O[nt][j] = 0.f;

    const uint32_t kRow = (uint32_t)(lane & 7);
    const uint32_t kColSel = (uint32_t)(((lane >> 3) & 1) * 16);
    const int nsteps = qt * 2 + 2;

    for (int s = 0; s < nsteps; ++s) {
        const int kv0 = s * 64;
        {
            const __nv_bfloat16* pkh = kh + ((size_t)bh * TT + kv0) * DD;
            const __nv_bfloat16* pkl = kl + ((size_t)bh * TT + kv0) * DD;
            const __nv_bfloat16* pvh = vh + ((size_t)bh * TT + kv0) * DD;
            const __nv_bfloat16* pvl = vl + ((size_t)bh * TT + kv0) * DD;
#pragma unroll
            for (int it = 0; it < 2; ++it) {
                int id = tid + it * 256;          // 0..511
                int row = id >> 3, seg = id & 7;
                size_t go = (size_t)row * DD + seg * 8;
                int so = row * FROWB + seg * 16;
                *(uint4*)(sKhi + so) = *(const uint4*)(pkh + go);
                *(uint4*)(sKlo + so) = *(const uint4*)(pkl + go);
                *(uint4*)(sVhi + so) = *(const uint4*)(pvh + go);
                *(uint4*)(sVlo + so) = *(const uint4*)(pvl + go);
            }
        }
        __syncthreads();

        // ---- S = Q K^T (split 3-pass) ----
        float S[8][4];
#pragma unroll
        for (int nt = 0; nt < 8; ++nt)
#pragma unroll
            for (int j = 0; j < 4; ++j) S[nt][j] = 0.f;
#pragma unroll
        for (int kc = 0; kc < 4; ++kc) {
#pragma unroll
            for (int nt = 0; nt < 8; ++nt) {
                uint32_t kbh[2], kbl[2];
                uint32_t off = (uint32_t)((nt * 8 + kRow) * FROWB) + kc * 32 + kColSel;
                ldsm_x2(kbh[0], kbh[1], uKhi + off);
                ldsm_x2(kbl[0], kbl[1], uKlo + off);
                mma_bf16(S[nt], qfh[kc], kbh);
                mma_bf16(S[nt], qfh[kc], kbl);
                mma_bf16(S[nt], qfl[kc], kbh);
            }
        }

        // ---- causal mask ----
        if (kv0 + 63 > rowbase) {
            int r0 = rowbase + (lane >> 2), r1 = r0 + 8;
            int cb = kv0 + 2 * (lane & 3);
#pragma unroll
            for (int nt = 0; nt < 8; ++nt) {
                int c0 = cb + nt * 8, c1 = c0 + 1;
                if (c0 > r0) S[nt][0] = -1e30f;
                if (c1 > r0) S[nt][1] = -1e30f;
                if (c0 > r1) S[nt][2] = -1e30f;
                if (c1 > r1) S[nt][3] = -1e30f;
            }
        }

        // ---- online softmax (per-warp, register-only) ----
        float mx0 = -1e30f, mx1 = -1e30f;
#pragma unroll
        for (int nt = 0; nt < 8; ++nt) {
            mx0 = fmaxf(mx0, fmaxf(S[nt][0], S[nt][1]));
            mx1 = fmaxf(mx1, fmaxf(S[nt][2], S[nt][3]));
        }
        mx0 = fmaxf(mx0, __shfl_xor_sync(0xffffffffu, mx0, 1));
        mx0 = fmaxf(mx0, __shfl_xor_sync(0xffffffffu, mx0, 2));
        mx1 = fmaxf(mx1, __shfl_xor_sync(0xffffffffu, mx1, 1));
        mx1 = fmaxf(mx1, __shfl_xor_sync(0xffffffffu, mx1, 2));
        float mn0 = fmaxf(mrow0, mx0), mn1 = fmaxf(mrow1, mx1);
        float a0 = __expf(mrow0 - mn0), a1 = __expf(mrow1 - mn1);
        float rs0 = 0.f, rs1 = 0.f;
#pragma unroll
        for (int nt = 0; nt < 8; ++nt) {
            S[nt][0] = __expf(S[nt][0] - mn0); rs0 += S[nt][0];
            S[nt][1] = __expf(S[nt][1] - mn0); rs0 += S[nt][1];
            S[nt][2] = __expf(S[nt][2] - mn1); rs1 += S[nt][2];
            S[nt][3] = __expf(S[nt][3] - mn1); rs1 += S[nt][3];
        }
        rs0 += __shfl_xor_sync(0xffffffffu, rs0, 1);
        rs0 += __shfl_xor_sync(0xffffffffu, rs0, 2);
        rs1 += __shfl_xor_sync(0xffffffffu, rs1, 1);
        rs1 += __shfl_xor_sync(0xffffffffu, rs1, 2);
        lrow0 = lrow0 * a0 + rs0;
        lrow1 = lrow1 * a1 + rs1;
        mrow0 = mn0; mrow1 = mn1;
#pragma unroll
        for (int nt = 0; nt < 8; ++nt) {
            O[nt][0] *= a0; O[nt][1] *= a0; O[nt][2] *= a1; O[nt][3] *= a1;
        }

        // ---- O += P V (split 3-pass; P frag built in regs from S) ----
#pragma unroll
        for (int kc = 0; kc < 4; ++kc) {
            int t0 = 2 * kc, t1 = 2 * kc + 1;
            uint32_t phi[4], plo[4];
            phi[0] = pack2(S[t0][0], S[t0][1]);
            phi[1] = pack2(S[t0][2], S[t0][3]);
            phi[2] = pack2(S[t1][0], S[t1][1]);
            phi[3] = pack2(S[t1][2], S[t1][3]);
            plo[0] = pack2(S[t0][0] - __bfloat162float(__float2bfloat16(S[t0][0])),
                           S[t0][1] - __bfloat162float(__float2bfloat16(S[t0][1])));
            plo[1] = pack2(S[t0][2] - __bfloat162float(__float2bfloat16(S[t0][2])),
                           S[t0][3] - __bfloat162float(__float2bfloat16(S[t0][3])));
            plo[2] = pack2(S[t1][0] - __bfloat162float(__float2bfloat16(S[t1][0])),
                           S[t1][1] - __bfloat162float(__float2bfloat16(S[t1][1])));
            plo[3] = pack2(S[t1][2] - __bfloat162float(__float2bfloat16(S[t1][2])),
                           S[t1][3] - __bfloat162float(__float2bfloat16(S[t1][3])));
            uint32_t vRow = (uint32_t)((kc * 16 + (lane & 15)) * FROWB);
#pragma unroll
            for (int nt = 0; nt < 8; ++nt) {
                uint32_t vbh[2], vbl[2];
                uint32_t off = vRow + nt * 16;
                ldsm_x2t(vbh[0], vbh[1], uVhi + off);
                ldsm_x2t(vbl[0], vbl[1], uVlo + off);
                mma_bf16(O[nt], phi, vbh);
                mma_bf16(O[nt], phi, vbl);
                mma_bf16(O[nt], plo, vbh);
            }
        }
        __syncthreads();
    }

    // ---- epilogue: attn[tok][h*64+d] = O / l ----
    const int b = bh >> 4, hh = bh & 15;
    const float il0 = 1.0f / lrow0, il1 = 1.0f / lrow1;
    const int r0 = rowbase + (lane >> 2);
    const size_t tok0 = (size_t)b * TT + r0;
#pragma unroll
    for (int nt = 0; nt < 8; ++nt) {
        int c = hh * DD + nt * 8 + 2 * (lane & 3);
        float2 o0 = { O[nt][0] * il0, O[nt][1] * il0 };
        float2 o1 = { O[nt][2] * il1, O[nt][3] * il1 };
        *(float2*)(attn + tok0 * CC + c) = o0;
        *(float2*)(attn + (tok0 + 8) * CC + c) = o1;
    }
}

// ================= split fp32 -> (hi, lo) bf16 =================
__global__ __launch_bounds__(256) void split_kernel(
    const float* __restrict__ src, __nv_bfloat16* __restrict__ hi,
    __nv_bfloat16* __restrict__ lo, size_t n4)
{
    size_t i = (size_t)blockIdx.x * blockDim.x + threadIdx.x;
    if (i >= n4) return;
    float4 v = ((const float4*)src)[i];
    __nv_bfloat16 h0 = __float2bfloat16(v.x), h1 = __float2bfloat16(v.y);
    __nv_bfloat16 h2 = __float2bfloat16(v.z), h3 = __float2bfloat16(v.w);
    __nv_bfloat16 l0 = __float2bfloat16(v.x - __bfloat162float(h0));
    __nv_bfloat16 l1 = __float2bfloat16(v.y - __bfloat162float(h1));
    __nv_bfloat16 l2 = __float2bfloat16(v.z - __bfloat162float(h2));
    __nv_bfloat16 l3 = __float2bfloat16(v.w - __bfloat162float(h3));
    ((__nv_bfloat162*)hi)[2 * i]     = __nv_bfloat162(h0, h1);
    ((__nv_bfloat162*)hi)[2 * i + 1] = __nv_bfloat162(h2, h3);
    ((__nv_bfloat162*)lo)[2 * i]     = __nv_bfloat162(l0, l1);
    ((__nv_bfloat162*)lo)[2 * i + 1] = __nv_bfloat162(l2, l3);
}

// ================= transpose + split weights =================
__global__ __launch_bounds__(256) void transpose_split_kernel(
    const float* __restrict__ W, __nv_bfloat16* __restrict__ hi,
    __nv_bfloat16* __restrict__ lo, int K, int N)
{
    __shared__ float t[32][33];
    int tx = threadIdx.x, ty = threadIdx.y;
    int n0 = blockIdx.x * 32, k0 = blockIdx.y * 32;
#pragma unroll
    for (int i = 0; i < 4; ++i)
        t[ty + i * 8][tx] = W[(size_t)(k0 + ty + i * 8) * N + n0 + tx];
    __syncthreads();
#pragma unroll
    for (int i = 0; i < 4; ++i) {
        int n = n0 + ty + i * 8, k = k0 + tx;
        float v = t[tx][ty + i * 8];
        __nv_bfloat16 h = __float2bfloat16(v);
        hi[(size_t)n * K + k] = h;
        lo[(size_t)n * K + k] = __float2bfloat16(v - __bfloat162float(h));
    }
}

// ================= RMSNorm + RoPE -> split bf16 outputs =================
__global__ __launch_bounds__(256) void rmsrope_kernel(
    const float* __restrict__ qkv,
    __nv_bfloat16* __restrict__ qhi, __nv_bfloat16* __restrict__ qlo,
    __nv_bfloat16* __restrict__ khi, __nv_bfloat16* __restrict__ klo,
    __nv_bfloat16* __restrict__ vhi, __nv_bfloat16* __restrict__ vlo,
    float* __restrict__ vout)
{
    int gw   = (int)((blockIdx.x * blockDim.x + threadIdx.x) >> 5);
    int lane = threadIdx.x & 31;
    if (gw >= BH * TT) return;
    int t = gw % TT;
    int h = (gw / TT) % HH;
    int b = gw / (TT * HH);

    size_t tok = (size_t)b * TT + t;
    const float* base = qkv + tok * C3 + h * DD;
    size_t oidx = ((size_t)(b * HH + h) * TT + t) * DD;

    float ex  = (float)lane * (1.0f / 32.0f);
    float inv = expf(-ex * 9.210340371976184f);
    float ang = (float)t * inv;
    float cs, sn;
    sincosf(ang, &cs, &sn);

    // q (scaled by 1/8 before split)
    {
        float x1 = base[lane], x2 = base[lane + 32];
        float ss = x1 * x1 + x2 * x2;
#pragma unroll
        for (int off = 16; off; off >>= 1) ss += __shfl_xor_sync(0xffffffffu, ss, off);
        float r = rsqrtf(ss * (1.0f / 64.0f) + 1e-6f) * 0.125f;
        x1 *= r; x2 *= r;
        float o1 = x1 * cs - x2 * sn;
        float o2 = x1 * sn + x2 * cs;
        __nv_bfloat16 h1 = __float2bfloat16(o1), h2 = __float2bfloat16(o2);
        qhi[oidx + lane]      = h1;
        qhi[oidx + lane + 32] = h2;
        qlo[oidx + lane]      = __float2bfloat16(o1 - __bfloat162float(h1));
        qlo[oidx + lane + 32] = __float2bfloat16(o2 - __bfloat162float(h2));
    }
    // k
    {
        const float* kb = base + CC;
        float x1 = kb[lane], x2 = kb[lane + 32];
        float ss = x1 * x1 + x2 * x2;
#pragma unroll
        for (int off = 16; off; off >>= 1) ss += __shfl_xor_sync(0xffffffffu, ss, off);
        float r = rsqrtf(ss * (1.0f / 64.0f) + 1e-6f);
        x1 *= r; x2 *= r;
        float o1 = x1 * cs - x2 * sn;
        float o2 = x1 * sn + x2 * cs;
        __nv_bfloat16 h1 = __float2bfloat16(o1), h2 = __float2bfloat16(o2);
        khi[oidx + lane]      = h1;
        khi[oidx + lane + 32] = h2;
        klo[oidx + lane]      = __float2bfloat16(o1 - __bfloat162float(h1));
        klo[oidx + lane + 32] = __float2bfloat16(o2 - __bfloat162float(h2));
    }
    // v: fp32 passthrough + split
    {
        float v1 = base[2 * CC + lane], v2 = base[2 * CC + lane + 32];
        vout[oidx + lane]      = v1;
        vout[oidx + lane + 32] = v2;
        __nv_bfloat16 h1 = __float2bfloat16(v1), h2 = __float2bfloat16(v2);
        vhi[oidx + lane]      = h1;
        vhi[oidx + lane + 32] = h2;
        vlo[oidx + lane]      = __float2bfloat16(v1 - __bfloat162float(h1));
        vlo[oidx + lane + 32] = __float2bfloat16(v2 - __bfloat162float(h2));
    }
}

// ---------------- value copy ----------------
__global__ __launch_bounds__(256) void copy_kernel(
    const float* __restrict__ src, float* __restrict__ dst, size_t n4)
{
    size_t i = (size_t)blockIdx.x * blockDim.x + threadIdx.x;
    if (i < n4) ((float4*)dst)[i] = ((const float4*)src)[i];
}

// ================= launch =================
extern "C" void kernel_launch(void* const* d_in, const int* in_sizes, int n_in,
                              void* d_out, int out_size)
{
    const float* x = nullptr; const float* Wqkv = nullptr; const float* bqkv = nullptr;
    const float* Wproj = nullptr; const float* bproj = nullptr;
    for (int i = 0; i < n_in; ++i) {
        switch (in_sizes[i]) {
            case 8388608: x     = (const float*)d_in[i]; break;
            case 3145728: Wqkv  = (const float*)d_in[i]; break;
            case 3072:    bqkv  = (const float*)d_in[i]; break;
            case 1048576: Wproj = (const float*)d_in[i]; break;
            case 1024:    bproj = (const float*)d_in[i]; break;
            default: break; // lamb: exact identity, unused
        }
    }

    float* out = (float*)d_out;

    float *qkv, *vn, *attn;
    __nv_bfloat16 *xhi, *xlo, *wqhi, *wqlo, *wphi, *wplo, *ahi, *alo;
    __nv_bfloat16 *qh_, *ql_, *kh_, *kl_, *vh_, *vl_;
    cudaGetSymbolAddress((void**)&qkv, g_qkv);
    cudaGetSymbolAddress((void**)&vn,  g_vn);
    cudaGetSymbolAddress((void**)&attn, g_attn);
    cudaGetSymbolAddress((void**)&xhi, g_xhi);
    cudaGetSymbolAddress((void**)&xlo, g_xlo);
    cudaGetSymbolAddress((void**)&wqhi, g_wqT_hi);
    cudaGetSymbolAddress((void**)&wqlo, g_wqT_lo);
    cudaGetSymbolAddress((void**)&wphi, g_wpT_hi);
    cudaGetSymbolAddress((void**)&wplo, g_wpT_lo);
    cudaGetSymbolAddress((void**)&ahi, g_ahi);
    cudaGetSymbolAddress((void**)&alo, g_alo);
    cudaGetSymbolAddress((void**)&qh_, g_qh);
    cudaGetSymbolAddress((void**)&ql_, g_ql);
    cudaGetSymbolAddress((void**)&kh_, g_kh);
    cudaGetSymbolAddress((void**)&kl_, g_kl);
    cudaGetSymbolAddress((void**)&vh_, g_vh);
    cudaGetSymbolAddress((void**)&vl_, g_vl);

    cudaFuncSetAttribute(mma_gemm_kernel, cudaFuncAttributeMaxDynamicSharedMemorySize, GEMM_SMEM);

    // 0) operand prep
    {
        size_t n4 = ((size_t)NTOK * CC) / 4;
        split_kernel<<<(unsigned)((n4 + 255) / 256), 256>>>(x, xhi, xlo, n4);
    }
    transpose_split_kernel<<<dim3(C3 / 32, CC / 32), dim3(32, 8)>>>(Wqkv, wqhi, wqlo, CC, C3);
    transpose_split_kernel<<<dim3(CC / 32, CC / 32), dim3(32, 8)>>>(Wproj, wphi, wplo, CC, CC);

    // 1) QKV = x @ Wqkv + bqkv
    mma_gemm_kernel<<<dim3(C3 / 128, NTOK / 128), 256, GEMM_SMEM>>>(
        xhi, xlo, wqhi, wqlo, bqkv, qkv, NTOK, C3, CC);

    // 2) rmsnorm + rope -> split bf16 q/k/v (+ fp32 v)
    rmsrope_kernel<<<(BH * TT) / 8, 256>>>(qkv, qh_, ql_, kh_, kl_, vh_, vl_, vn);

    // 3) tensor-core causal flash attention
    flash_tc_kernel<<<dim3(TT / 128, BH), 256>>>(qh_, ql_, kh_, kl_, vh_, vl_, attn);

    // 4) split attn, then out = attn @ Wproj + bproj
    {
        size_t n4 = ((size_t)NTOK * CC) / 4;
        split_kernel<<<(unsigned)((n4 + 255) / 256), 256>>>(attn, ahi, alo, n4);
    }
    mma_gemm_kernel<<<dim3(CC / 128, NTOK / 128), 256, GEMM_SMEM>>>(
        ahi, alo, wphi, wplo, bproj, out, NTOK, CC, CC);

    // 5) value output
    if ((size_t)out_size >= 2 * OUT0_ELEMS) {
        size_t n4 = OUT0_ELEMS / 4;
        copy_kernel<<<(unsigned)((n4 + 255) / 256), 256>>>(vn, out + OUT0_ELEMS, n4);
    }
}

// round 12
// speedup vs baseline: 2.4264x; 1.0572x over previous
#include <cuda_runtime.h>
#include <cuda_bf16.h>
#include <math.h>
#include <stddef.h>
#include <stdint.h>

#define BB 4
#define TT 2048
#define CC 1024
#define HH 16
#define DD 64
#define BH (BB*HH)
#define NTOK (BB*TT)     /* 8192 */
#define C3   (3*CC)      /* 3072 */
#define OUT0_ELEMS ((size_t)BB*TT*CC)   /* 8388608 */

// ---------------- scratch ----------------
__device__ float g_qkv [(size_t)NTOK * C3];
__device__ float g_vn  [(size_t)BH*TT*DD];          // fallback value target
// bf16 split operands
__device__ __nv_bfloat16 g_xhi[(size_t)NTOK*CC];
__device__ __nv_bfloat16 g_xlo[(size_t)NTOK*CC];
__device__ __nv_bfloat16 g_wqT_hi[(size_t)C3*CC];
__device__ __nv_bfloat16 g_wqT_lo[(size_t)C3*CC];
__device__ __nv_bfloat16 g_wpT_hi[(size_t)CC*CC];
__device__ __nv_bfloat16 g_wpT_lo[(size_t)CC*CC];
__device__ __nv_bfloat16 g_ahi[(size_t)NTOK*CC];
__device__ __nv_bfloat16 g_alo[(size_t)NTOK*CC];
// flash operands (head-major [bh][t][d]); q pre-scaled by 1/8
__device__ __nv_bfloat16 g_qh[(size_t)BH*TT*DD];
__device__ __nv_bfloat16 g_ql[(size_t)BH*TT*DD];
__device__ __nv_bfloat16 g_kh[(size_t)BH*TT*DD];
__device__ __nv_bfloat16 g_kl[(size_t)BH*TT*DD];
__device__ __nv_bfloat16 g_vh[(size_t)BH*TT*DD];
__device__ __nv_bfloat16 g_vl[(size_t)BH*TT*DD];

// ================= helpers =================
__device__ __forceinline__ uint32_t smem_u32(const void* p) {
    uint32_t a;
    asm("{ .reg .u64 t; cvta.to.shared.u64 t, %1; cvt.u32.u64 %0, t; }" : "=r"(a) : "l"(p));
    return a;
}
__device__ __forceinline__ void ldsm_x4(uint32_t& a0, uint32_t& a1, uint32_t& a2, uint32_t& a3, uint32_t addr) {
    asm volatile("ldmatrix.sync.aligned.m8n8.x4.shared.b16 {%0,%1,%2,%3}, [%4];"
                 : "=r"(a0), "=r"(a1), "=r"(a2), "=r"(a3) : "r"(addr));
}
__device__ __forceinline__ void ldsm_x2(uint32_t& b0, uint32_t& b1, uint32_t addr) {
    asm volatile("ldmatrix.sync.aligned.m8n8.x2.shared.b16 {%0,%1}, [%2];"
                 : "=r"(b0), "=r"(b1) : "r"(addr));
}
__device__ __forceinline__ void ldsm_x2t(uint32_t& b0, uint32_t& b1, uint32_t addr) {
    asm volatile("ldmatrix.sync.aligned.m8n8.x2.trans.shared.b16 {%0,%1}, [%2];"
                 : "=r"(b0), "=r"(b1) : "r"(addr));
}
__device__ __forceinline__ void mma_bf16(float* c, const uint32_t* a, const uint32_t* b) {
    asm volatile("mma.sync.aligned.m16n8k16.row.col.f32.bf16.bf16.f32 "
                 "{%0,%1,%2,%3}, {%4,%5,%6,%7}, {%8,%9}, {%0,%1,%2,%3};"
                 : "+f"(c[0]), "+f"(c[1]), "+f"(c[2]), "+f"(c[3])
                 : "r"(a[0]), "r"(a[1]), "r"(a[2]), "r"(a[3]), "r"(b[0]), "r"(b[1]));
}
#define CPASYNC16(dst, src) asm volatile("cp.async.cg.shared.global [%0], [%1], 16;" :: "r"(dst), "l"(src))
#define CPCOMMIT()          asm volatile("cp.async.commit_group;" ::: "memory")
#define CPWAIT(n)           asm volatile("cp.async.wait_group %0;" :: "n"(n) : "memory")

__device__ __forceinline__ uint32_t pack2(float x, float y) {
    __nv_bfloat162 t = __nv_bfloat162(__float2bfloat16(x), __float2bfloat16(y));
    return *(uint32_t*)&t;
}

// ================= cp.async double-buffered mma GEMM: C = A @ B^T + bias =================
#define ROWB 80
#define BUFB (128 * ROWB)     /* 10240 */
#define STAGE (4 * BUFB)      /* 40960 */
#define GEMM_SMEM (2 * STAGE) /* 81920 */

__global__ __launch_bounds__(256) void mma_gemm_kernel(
    const __nv_bfloat16* __restrict__ Ahi, const __nv_bfloat16* __restrict__ Alo,
    const __nv_bfloat16* __restrict__ Bhi, const __nv_bfloat16* __restrict__ Blo,
    const float* __restrict__ bias, float* __restrict__ C,
    int M, int N, int K)
{
    extern __shared__ __align__(16) char dsm[];
    const int tid = threadIdx.x;
    const int wid = tid >> 5, lane = tid & 31;
    const int wm = wid & 1, wn = wid >> 1;
    const int m0 = blockIdx.y * 128, n0 = blockIdx.x * 128;
    const uint32_t ubase = smem_u32(dsm);

    float acc[4][4][4];
#pragma unroll
    for (int i = 0; i < 4; ++i)
#pragma unroll
        for (int j = 0; j < 4; ++j)
#pragma unroll
            for (int r = 0; r < 4; ++r) acc[i][j][r] = 0.f;

    const uint32_t aRow = (uint32_t)(lane & 15);
    const uint32_t aColSel = (uint32_t)(((lane >> 4) & 1) * 16);
    const uint32_t bRow = (uint32_t)(lane & 7);
    const uint32_t bColSel = (uint32_t)(((lane >> 3) & 1) * 16);

    const int id0 = tid, id1 = tid + 256;
    const int r0i = id0 >> 2, s0i = id0 & 3, r1i = id1 >> 2, s1i = id1 & 3;

    auto issue = [&](int kt, int sel) {
        const __nv_bfloat16* pa_hi = Ahi + (size_t)m0 * K + kt * 32;
        const __nv_bfloat16* pa_lo = Alo + (size_t)m0 * K + kt * 32;
        const __nv_bfloat16* pb_hi = Bhi + (size_t)n0 * K + kt * 32;
        const __nv_bfloat16* pb_lo = Blo + (size_t)n0 * K + kt * 32;
        uint32_t sb = ubase + sel * STAGE;
        {
            size_t go = (size_t)r0i * K + s0i * 8;
            uint32_t so = (uint32_t)(r0i * ROWB + s0i * 16);
            CPASYNC16(sb + so,            (const char*)(pa_hi + go));
            CPASYNC16(sb + BUFB + so,     (const char*)(pa_lo + go));
            CPASYNC16(sb + 2*BUFB + so,   (const char*)(pb_hi + go));
            CPASYNC16(sb + 3*BUFB + so,   (const char*)(pb_lo + go));
        }
        {
            size_t go = (size_t)r1i * K + s1i * 8;
            uint32_t so = (uint32_t)(r1i * ROWB + s1i * 16);
            CPASYNC16(sb + so,            (const char*)(pa_hi + go));
            CPASYNC16(sb + BUFB + so,     (const char*)(pa_lo + go));
            CPASYNC16(sb + 2*BUFB + so,   (const char*)(pb_hi + go));
            CPASYNC16(sb + 3*BUFB + so,   (const char*)(pb_lo + go));
        }
    };

    const int KT = K / 32;
    issue(0, 0);
    CPCOMMIT();

    for (int kt = 0; kt < KT; ++kt) {
        if (kt + 1 < KT) { issue(kt + 1, (kt + 1) & 1); CPCOMMIT(); CPWAIT(1); }
        else             { CPWAIT(0); }
        __syncthreads();

        uint32_t sb = ubase + (kt & 1) * STAGE;
        uint32_t uAhi = sb, uAlo = sb + BUFB, uBhi = sb + 2*BUFB, uBlo = sb + 3*BUFB;
#pragma unroll
        for (int kh = 0; kh < 2; ++kh) {
            uint32_t ahi[4][4], alo[4][4], bhi[4][2], blo[4][2];
#pragma unroll
            for (int mt = 0; mt < 4; ++mt) {
                uint32_t off = (uint32_t)((wm * 64 + mt * 16 + aRow) * ROWB) + kh * 32 + aColSel;
                ldsm_x4(ahi[mt][0], ahi[mt][1], ahi[mt][2], ahi[mt][3], uAhi + off);
                ldsm_x4(alo[mt][0], alo[mt][1], alo[mt][2], alo[mt][3], uAlo + off);
            }
#pragma unroll
            for (int nt = 0; nt < 4; ++nt) {
                uint32_t off = (uint32_t)((wn * 32 + nt * 8 + bRow) * ROWB) + kh * 32 + bColSel;
                ldsm_x2(bhi[nt][0], bhi[nt][1], uBhi + off);
                ldsm_x2(blo[nt][0], blo[nt][1], uBlo + off);
            }
#pragma unroll
            for (int mt = 0; mt < 4; ++mt)
#pragma unroll
                for (int nt = 0; nt < 4; ++nt) {
                    mma_bf16(acc[mt][nt], ahi[mt], bhi[nt]);
                    mma_bf16(acc[mt][nt], ahi[mt], blo[nt]);
                    mma_bf16(acc[mt][nt], alo[mt], bhi[nt]);
                }
        }
        __syncthreads();
    }

    const int rbase = m0 + wm * 64 + (lane >> 2);
    const int cbase = n0 + wn * 32 + (lane & 3) * 2;
#pragma unroll
    for (int mt = 0; mt < 4; ++mt)
#pragma unroll
        for (int nt = 0; nt < 4; ++nt) {
            int r = rbase + mt * 16;
            int c = cbase + nt * 8;
            float2 bv = *(const float2*)(bias + c);
            float2 o0 = { acc[mt][nt][0] + bv.x, acc[mt][nt][1] + bv.y };
            float2 o1 = { acc[mt][nt][2] + bv.x, acc[mt][nt][3] + bv.y };
            *(float2*)(C + (size_t)r * N + c) = o0;
            *(float2*)(C + (size_t)(r + 8) * N + c) = o1;
        }
}

// ================= tensor-core flash attention (cp.async 2-stage, fused split epilogue) =================
#define FROWB 144
#define FBUF (64 * FROWB)     /* 9216 */
#define FSTAGE (4 * FBUF)     /* 36864 */
#define FL_SMEM (2 * FSTAGE)  /* 73728 */

__global__ __launch_bounds__(256) void flash_tc_kernel(
    const __nv_bfloat16* __restrict__ qh, const __nv_bfloat16* __restrict__ ql,
    const __nv_bfloat16* __restrict__ kh, const __nv_bfloat16* __restrict__ kl,
    const __nv_bfloat16* __restrict__ vh, const __nv_bfloat16* __restrict__ vl,
    __nv_bfloat16* __restrict__ ahi, __nv_bfloat16* __restrict__ alo)
{
    extern __shared__ __align__(16) char fsm[];
    const uint32_t ubase = smem_u32(fsm);

    const int qt = blockIdx.x;
    const int bh = blockIdx.y;
    const int tid = threadIdx.x;
    const int wid = tid >> 5, lane = tid & 31;
    const int Q0 = qt * 128;
    const int rowbase = Q0 + wid * 16;

    // ---- stage Q into stage-0 buffers (rows0-63 -> K bufs, rows64-127 -> V bufs) ----
    {
        const __nv_bfloat16* qbh = qh + ((size_t)bh * TT + Q0) * DD;
        const __nv_bfloat16* qbl = ql + ((size_t)bh * TT + Q0) * DD;
#pragma unroll
        for (int it = 0; it < 4; ++it) {
            int id = tid + it * 256;
            int row = id >> 3, seg = id & 7;
            size_t go = (size_t)row * DD + seg * 8;
            int drow = row & 63;
            uint32_t dh = ubase + ((row < 64) ? 0 : 2 * FBUF) + drow * FROWB + seg * 16;
            uint32_t dl = dh + FBUF;
            *(uint4*)(fsm + (dh - ubase)) = *(const uint4*)(qbh + go);
            *(uint4*)(fsm + (dl - ubase)) = *(const uint4*)(qbl + go);
        }
    }
    __syncthreads();

    // Q fragments (persist in regs)
    uint32_t qfh[4][4], qfl[4][4];
    {
        uint32_t bufh = ubase + ((wid < 4) ? 0 : 2 * FBUF);
        uint32_t bufl = bufh + FBUF;
        uint32_t rsel = (uint32_t)(((wid & 3) * 16 + (lane & 15)) * FROWB);
        uint32_t csel = (uint32_t)(((lane >> 4) & 1) * 16);
#pragma unroll
        for (int kc = 0; kc < 4; ++kc) {
            uint32_t off = rsel + kc * 32 + csel;
            ldsm_x4(qfh[kc][0], qfh[kc][1], qfh[kc][2], qfh[kc][3], bufh + off);
            ldsm_x4(qfl[kc][0], qfl[kc][1], qfl[kc][2], qfl[kc][3], bufl + off);
        }
    }
    __syncthreads();

    float mrow0 = -1e30f, mrow1 = -1e30f, lrow0 = 0.f, lrow1 = 0.f;
    float O[8][4];
#pragma unroll
    for (int nt = 0; nt < 8; ++nt)
#pragma unroll
        for (int j = 0; j < 4; ++j) O[nt][j] = 0.f;

    const uint32_t kRow = (uint32_t)(lane & 7);
    const uint32_t kColSel = (uint32_t)(((lane >> 3) & 1) * 16);
    const int nsteps = qt * 2 + 2;

    const int idA = tid, idB = tid + 256;
    const int rA = idA >> 3, sA = idA & 7, rB = idB >> 3, sB = idB & 7;

    auto issue = [&](int s, int sel) {
        const int kv0 = s * 64;
        const __nv_bfloat16* pkh = kh + ((size_t)bh * TT + kv0) * DD;
        const __nv_bfloat16* pkl = kl + ((size_t)bh * TT + kv0) * DD;
        const __nv_bfloat16* pvh = vh + ((size_t)bh * TT + kv0) * DD;
        const __nv_bfloat16* pvl = vl + ((size_t)bh * TT + kv0) * DD;
        uint32_t sb = ubase + sel * FSTAGE;
        {
            size_t go = (size_t)rA * DD + sA * 8;
            uint32_t so = (uint32_t)(rA * FROWB + sA * 16);
            CPASYNC16(sb + so,            (const char*)(pkh + go));
            CPASYNC16(sb + FBUF + so,     (const char*)(pkl + go));
            CPASYNC16(sb + 2*FBUF + so,   (const char*)(pvh + go));
            CPASYNC16(sb + 3*FBUF + so,   (const char*)(pvl + go));
        }
        {
            size_t go = (size_t)rB * DD + sB * 8;
            uint32_t so = (uint32_t)(rB * FROWB + sB * 16);
            CPASYNC16(sb + so,            (const char*)(pkh + go));
            CPASYNC16(sb + FBUF + so,     (const char*)(pkl + go));
            CPASYNC16(sb + 2*FBUF + so,   (const char*)(pvh + go));
            CPASYNC16(sb + 3*FBUF + so,   (const char*)(pvl + go));
        }
    };

    issue(0, 0);
    CPCOMMIT();

    for (int s = 0; s < nsteps; ++s) {
        const int kv0 = s * 64;
        if (s + 1 < nsteps) { issue(s + 1, (s + 1) & 1); CPCOMMIT(); CPWAIT(1); }
        else                { CPWAIT(0); }
        __syncthreads();

        uint32_t sb = ubase + (s & 1) * FSTAGE;
        uint32_t uKhi = sb, uKlo = sb + FBUF, uVhi = sb + 2*FBUF, uVlo = sb + 3*FBUF;

        // ---- S = Q K^T (split 3-pass) ----
        float S[8][4];
#pragma unroll
        for (int nt = 0; nt < 8; ++nt)
#pragma unroll
            for (int j = 0; j < 4; ++j) S[nt][j] = 0.f;
#pragma unroll
        for (int kc = 0; kc < 4; ++kc) {
#pragma unroll
            for (int nt = 0; nt < 8; ++nt) {
                uint32_t kbh[2], kbl[2];
                uint32_t off = (uint32_t)((nt * 8 + kRow) * FROWB) + kc * 32 + kColSel;
                ldsm_x2(kbh[0], kbh[1], uKhi + off);
                ldsm_x2(kbl[0], kbl[1], uKlo + off);
                mma_bf16(S[nt], qfh[kc], kbh);
                mma_bf16(S[nt], qfh[kc], kbl);
                mma_bf16(S[nt], qfl[kc], kbh);
            }
        }

        // ---- causal mask ----
        if (kv0 + 63 > rowbase) {
            int r0 = rowbase + (lane >> 2), r1 = r0 + 8;
            int cb = kv0 + 2 * (lane & 3);
#pragma unroll
            for (int nt = 0; nt < 8; ++nt) {
                int c0 = cb + nt * 8, c1 = c0 + 1;
                if (c0 > r0) S[nt][0] = -1e30f;
                if (c1 > r0) S[nt][1] = -1e30f;
                if (c0 > r1) S[nt][2] = -1e30f;
                if (c1 > r1) S[nt][3] = -1e30f;
            }
        }

        // ---- online softmax (per-warp, register-only) ----
        float mx0 = -1e30f, mx1 = -1e30f;
#pragma unroll
        for (int nt = 0; nt < 8; ++nt) {
            mx0 = fmaxf(mx0, fmaxf(S[nt][0], S[nt][1]));
            mx1 = fmaxf(mx1, fmaxf(S[nt][2], S[nt][3]));
        }
        mx0 = fmaxf(mx0, __shfl_xor_sync(0xffffffffu, mx0, 1));
        mx0 = fmaxf(mx0, __shfl_xor_sync(0xffffffffu, mx0, 2));
        mx1 = fmaxf(mx1, __shfl_xor_sync(0xffffffffu, mx1, 1));
        mx1 = fmaxf(mx1, __shfl_xor_sync(0xffffffffu, mx1, 2));
        float mn0 = fmaxf(mrow0, mx0), mn1 = fmaxf(mrow1, mx1);
        float a0 = __expf(mrow0 - mn0), a1 = __expf(mrow1 - mn1);
        float rs0 = 0.f, rs1 = 0.f;
#pragma unroll
        for (int nt = 0; nt < 8; ++nt) {
            S[nt][0] = __expf(S[nt][0] - mn0); rs0 += S[nt][0];
            S[nt][1] = __expf(S[nt][1] - mn0); rs0 += S[nt][1];
            S[nt][2] = __expf(S[nt][2] - mn1); rs1 += S[nt][2];
            S[nt][3] = __expf(S[nt][3] - mn1); rs1 += S[nt][3];
        }
        rs0 += __shfl_xor_sync(0xffffffffu, rs0, 1);
        rs0 += __shfl_xor_sync(0xffffffffu, rs0, 2);
        rs1 += __shfl_xor_sync(0xffffffffu, rs1, 1);
        rs1 += __shfl_xor_sync(0xffffffffu, rs1, 2);
        lrow0 = lrow0 * a0 + rs0;
        lrow1 = lrow1 * a1 + rs1;
        mrow0 = mn0; mrow1 = mn1;
#pragma unroll
        for (int nt = 0; nt < 8; ++nt) {
            O[nt][0] *= a0; O[nt][1] *= a0; O[nt][2] *= a1; O[nt][3] *= a1;
        }

        // ---- O += P V (split 3-pass; P frag built in regs from S) ----
#pragma unroll
        for (int kc = 0; kc < 4; ++kc) {
            int t0 = 2 * kc, t1 = 2 * kc + 1;
            uint32_t phi[4], plo[4];
            phi[0] = pack2(S[t0][0], S[t0][1]);
            phi[1] = pack2(S[t0][2], S[t0][3]);
            phi[2] = pack2(S[t1][0], S[t1][1]);
            phi[3] = pack2(S[t1][2], S[t1][3]);
            plo[0] = pack2(S[t0][0] - __bfloat162float(__float2bfloat16(S[t0][0])),
                           S[t0][1] - __bfloat162float(__float2bfloat16(S[t0][1])));
            plo[1] = pack2(S[t0][2] - __bfloat162float(__float2bfloat16(S[t0][2])),
                           S[t0][3] - __bfloat162float(__float2bfloat16(S[t0][3])));
            plo[2] = pack2(S[t1][0] - __bfloat162float(__float2bfloat16(S[t1][0])),
                           S[t1][1] - __bfloat162float(__float2bfloat16(S[t1][1])));
            plo[3] = pack2(S[t1][2] - __bfloat162float(__float2bfloat16(S[t1][2])),
                           S[t1][3] - __bfloat162float(__float2bfloat16(S[t1][3])));
            uint32_t vRow = (uint32_t)((kc * 16 + (lane & 15)) * FROWB);
#pragma unroll
            for (int nt = 0; nt < 8; ++nt) {
                uint32_t vbh[2], vbl[2];
                uint32_t off = vRow + nt * 16;
                ldsm_x2t(vbh[0], vbh[1], uVhi + off);
                ldsm_x2t(vbl[0], vbl[1], uVlo + off);
                mma_bf16(O[nt], phi, vbh);
                mma_bf16(O[nt], phi, vbl);
                mma_bf16(O[nt], plo, vbh);
            }
        }
        __syncthreads();
    }

    // ---- fused epilogue: write split bf16 attn (hi/lo) directly ----
    const int b = bh >> 4, hh = bh & 15;
    const float il0 = 1.0f / lrow0, il1 = 1.0f / lrow1;
    const int r0 = rowbase + (lane >> 2);
    const size_t tok0 = (size_t)b * TT + r0;
#pragma unroll
    for (int nt = 0; nt < 8; ++nt) {
        int c = hh * DD + nt * 8 + 2 * (lane & 3);
        float o00 = O[nt][0] * il0, o01 = O[nt][1] * il0;
        float o10 = O[nt][2] * il1, o11 = O[nt][3] * il1;
        float h00 = __bfloat162float(__float2bfloat16(o00));
        float h01 = __bfloat162float(__float2bfloat16(o01));
        float h10 = __bfloat162float(__float2bfloat16(o10));
        float h11 = __bfloat162float(__float2bfloat16(o11));
        *(uint32_t*)(ahi + tok0 * CC + c)       = pack2(o00, o01);
        *(uint32_t*)(alo + tok0 * CC + c)       = pack2(o00 - h00, o01 - h01);
        *(uint32_t*)(ahi + (tok0 + 8) * CC + c) = pack2(o10, o11);
        *(uint32_t*)(alo + (tok0 + 8) * CC + c) = pack2(o10 - h10, o11 - h11);
    }
}

// ================= split fp32 -> (hi, lo) bf16 =================
__global__ __launch_bounds__(256) void split_kernel(
    const float* __restrict__ src, __nv_bfloat16* __restrict__ hi,
    __nv_bfloat16* __restrict__ lo, size_t n4)
{
    size_t i = (size_t)blockIdx.x * blockDim.x + threadIdx.x;
    if (i >= n4) return;
    float4 v = ((const float4*)src)[i];
    __nv_bfloat16 h0 = __float2bfloat16(v.x), h1 = __float2bfloat16(v.y);
    __nv_bfloat16 h2 = __float2bfloat16(v.z), h3 = __float2bfloat16(v.w);
    __nv_bfloat16 l0 = __float2bfloat16(v.x - __bfloat162float(h0));
    __nv_bfloat16 l1 = __float2bfloat16(v.y - __bfloat162float(h1));
    __nv_bfloat16 l2 = __float2bfloat16(v.z - __bfloat162float(h2));
    __nv_bfloat16 l3 = __float2bfloat16(v.w - __bfloat162float(h3));
    ((__nv_bfloat162*)hi)[2 * i]     = __nv_bfloat162(h0, h1);
    ((__nv_bfloat162*)hi)[2 * i + 1] = __nv_bfloat162(h2, h3);
    ((__nv_bfloat162*)lo)[2 * i]     = __nv_bfloat162(l0, l1);
    ((__nv_bfloat162*)lo)[2 * i + 1] = __nv_bfloat162(l2, l3);
}

// ================= transpose + split weights =================
__global__ __launch_bounds__(256) void transpose_split_kernel(
    const float* __restrict__ W, __nv_bfloat16* __restrict__ hi,
    __nv_bfloat16* __restrict__ lo, int K, int N)
{
    __shared__ float t[32][33];
    int tx = threadIdx.x, ty = threadIdx.y;
    int n0 = blockIdx.x * 32, k0 = blockIdx.y * 32;
#pragma unroll
    for (int i = 0; i < 4; ++i)
        t[ty + i * 8][tx] = W[(size_t)(k0 + ty + i * 8) * N + n0 + tx];
    __syncthreads();
#pragma unroll
    for (int i = 0; i < 4; ++i) {
        int n = n0 + ty + i * 8, k = k0 + tx;
        float v = t[tx][ty + i * 8];
        __nv_bfloat16 h = __float2bfloat16(v);
        hi[(size_t)n * K + k] = h;
        lo[(size_t)n * K + k] = __float2bfloat16(v - __bfloat162float(h));
    }
}

// ================= RMSNorm + RoPE -> split bf16 outputs + direct value write =================
__global__ __launch_bounds__(256) void rmsrope_kernel(
    const float* __restrict__ qkv,
    __nv_bfloat16* __restrict__ qhi, __nv_bfloat16* __restrict__ qlo,
    __nv_bfloat16* __restrict__ khi, __nv_bfloat16* __restrict__ klo,
    __nv_bfloat16* __restrict__ vhi, __nv_bfloat16* __restrict__ vlo,
    float* __restrict__ vout)
{
    int gw   = (int)((blockIdx.x * blockDim.x + threadIdx.x) >> 5);
    int lane = threadIdx.x & 31;
    if (gw >= BH * TT) return;
    int t = gw % TT;
    int h = (gw / TT) % HH;
    int b = gw / (TT * HH);

    size_t tok = (size_t)b * TT + t;
    const float* base = qkv + tok * C3 + h * DD;
    size_t oidx = ((size_t)(b * HH + h) * TT + t) * DD;

    float ex  = (float)lane * (1.0f / 32.0f);
    float inv = expf(-ex * 9.210340371976184f);
    float ang = (float)t * inv;
    float cs, sn;
    sincosf(ang, &cs, &sn);

    // q (scaled by 1/8 before split)
    {
        float x1 = base[lane], x2 = base[lane + 32];
        float ss = x1 * x1 + x2 * x2;
#pragma unroll
        for (int off = 16; off; off >>= 1) ss += __shfl_xor_sync(0xffffffffu, ss, off);
        float r = rsqrtf(ss * (1.0f / 64.0f) + 1e-6f) * 0.125f;
        x1 *= r; x2 *= r;
        float o1 = x1 * cs - x2 * sn;
        float o2 = x1 * sn + x2 * cs;
        __nv_bfloat16 h1 = __float2bfloat16(o1), h2 = __float2bfloat16(o2);
        qhi[oidx + lane]      = h1;
        qhi[oidx + lane + 32] = h2;
        qlo[oidx + lane]      = __float2bfloat16(o1 - __bfloat162float(h1));
        qlo[oidx + lane + 32] = __float2bfloat16(o2 - __bfloat162float(h2));
    }
    // k
    {
        const float* kb = base + CC;
        float x1 = kb[lane], x2 = kb[lane + 32];
        float ss = x1 * x1 + x2 * x2;
#pragma unroll
        for (int off = 16; off; off >>= 1) ss += __shfl_xor_sync(0xffffffffu, ss, off);
        float r = rsqrtf(ss * (1.0f / 64.0f) + 1e-6f);
        x1 *= r; x2 *= r;
        float o1 = x1 * cs - x2 * sn;
        float o2 = x1 * sn + x2 * cs;
        __nv_bfloat16 h1 = __float2bfloat16(o1), h2 = __float2bfloat16(o2);
        khi[oidx + lane]      = h1;
        khi[oidx + lane + 32] = h2;
        klo[oidx + lane]      = __float2bfloat16(o1 - __bfloat162float(h1));
        klo[oidx + lane + 32] = __float2bfloat16(o2 - __bfloat162float(h2));
    }
    // v: direct fp32 value output + split
    {
        float v1 = base[2 * CC + lane], v2 = base[2 * CC + lane + 32];
        vout[oidx + lane]      = v1;
        vout[oidx + lane + 32] = v2;
        __nv_bfloat16 h1 = __float2bfloat16(v1), h2 = __float2bfloat16(v2);
        vhi[oidx + lane]      = h1;
        vhi[oidx + lane + 32] = h2;
        vlo[oidx + lane]      = __float2bfloat16(v1 - __bfloat162float(h1));
        vlo[oidx + lane + 32] = __float2bfloat16(v2 - __bfloat162float(h2));
    }
}

// ================= launch =================
extern "C" void kernel_launch(void* const* d_in, const int* in_sizes, int n_in,
                              void* d_out, int out_size)
{
    const float* x = nullptr; const float* Wqkv = nullptr; const float* bqkv = nullptr;
    const float* Wproj = nullptr; const float* bproj = nullptr;
    for (int i = 0; i < n_in; ++i) {
        switch (in_sizes[i]) {
            case 8388608: x     = (const float*)d_in[i]; break;
            case 3145728: Wqkv  = (const float*)d_in[i]; break;
            case 3072:    bqkv  = (const float*)d_in[i]; break;
            case 1048576: Wproj = (const float*)d_in[i]; break;
            case 1024:    bproj = (const float*)d_in[i]; break;
            default: break; // lamb: exact identity, unused
        }
    }

    float* out = (float*)d_out;

    float *qkv, *vn;
    __nv_bfloat16 *xhi, *xlo, *wqhi, *wqlo, *wphi, *wplo, *ahi, *alo;
    __nv_bfloat16 *qh_, *ql_, *kh_, *kl_, *vh_, *vl_;
    cudaGetSymbolAddress((void**)&qkv, g_qkv);
    cudaGetSymbolAddress((void**)&vn,  g_vn);
    cudaGetSymbolAddress((void**)&xhi, g_xhi);
    cudaGetSymbolAddress((void**)&xlo, g_xlo);
    cudaGetSymbolAddress((void**)&wqhi, g_wqT_hi);
    cudaGetSymbolAddress((void**)&wqlo, g_wqT_lo);
    cudaGetSymbolAddress((void**)&wphi, g_wpT_hi);
    cudaGetSymbolAddress((void**)&wplo, g_wpT_lo);
    cudaGetSymbolAddress((void**)&ahi, g_ahi);
    cudaGetSymbolAddress((void**)&alo, g_alo);
    cudaGetSymbolAddress((void**)&qh_, g_qh);
    cudaGetSymbolAddress((void**)&ql_, g_ql);
    cudaGetSymbolAddress((void**)&kh_, g_kh);
    cudaGetSymbolAddress((void**)&kl_, g_kl);
    cudaGetSymbolAddress((void**)&vh_, g_vh);
    cudaGetSymbolAddress((void**)&vl_, g_vl);

    cudaFuncSetAttribute(mma_gemm_kernel, cudaFuncAttributeMaxDynamicSharedMemorySize, GEMM_SMEM);
    cudaFuncSetAttribute(flash_tc_kernel, cudaFuncAttributeMaxDynamicSharedMemorySize, FL_SMEM);

    // value output target: directly into d_out's second tuple slot if present
    float* value_out = ((size_t)out_size >= 2 * OUT0_ELEMS) ? (out + OUT0_ELEMS) : vn;

    // 0) operand prep
    {
        size_t n4 = ((size_t)NTOK * CC) / 4;
        split_kernel<<<(unsigned)((n4 + 255) / 256), 256>>>(x, xhi, xlo, n4);
    }
    transpose_split_kernel<<<dim3(C3 / 32, CC / 32), dim3(32, 8)>>>(Wqkv, wqhi, wqlo, CC, C3);
    transpose_split_kernel<<<dim3(CC / 32, CC / 32), dim3(32, 8)>>>(Wproj, wphi, wplo, CC, CC);

    // 1) QKV = x @ Wqkv + bqkv
    mma_gemm_kernel<<<dim3(C3 / 128, NTOK / 128), 256, GEMM_SMEM>>>(
        xhi, xlo, wqhi, wqlo, bqkv, qkv, NTOK, C3, CC);

    // 2) rmsnorm + rope -> split bf16 q/k/v; value written directly to output
    rmsrope_kernel<<<(BH * TT) / 8, 256>>>(qkv, qh_, ql_, kh_, kl_, vh_, vl_, value_out);

    // 3) tensor-core causal flash attention (fused split epilogue -> ahi/alo)
    flash_tc_kernel<<<dim3(TT / 128, BH), 256, FL_SMEM>>>(qh_, ql_, kh_, kl_, vh_, vl_, ahi, alo);

    // 4) out = attn @ Wproj + bproj
    mma_gemm_kernel<<<dim3(CC / 128, NTOK / 128), 256, GEMM_SMEM>>>(
        ahi, alo, wphi, wplo, bproj, out, NTOK, CC, CC);
}

// round 13
// speedup vs baseline: 2.4417x; 1.0063x over previous
#include <cuda_runtime.h>
#include <cuda_bf16.h>
#include <math.h>
#include <stddef.h>
#include <stdint.h>

#define BB 4
#define TT 2048
#define CC 1024
#define HH 16
#define DD 64
#define BH (BB*HH)
#define NTOK (BB*TT)     /* 8192 */
#define C3   (3*CC)      /* 3072 */
#define OUT0_ELEMS ((size_t)BB*TT*CC)   /* 8388608 */

// ---------------- scratch ----------------
__device__ float g_qkv [(size_t)NTOK * C3];
__device__ float g_vn  [(size_t)BH*TT*DD];          // fallback value target
// bf16 split operands
__device__ __nv_bfloat16 g_xhi[(size_t)NTOK*CC];
__device__ __nv_bfloat16 g_xlo[(size_t)NTOK*CC];
__device__ __nv_bfloat16 g_wqT_hi[(size_t)C3*CC];
__device__ __nv_bfloat16 g_wqT_lo[(size_t)C3*CC];
__device__ __nv_bfloat16 g_wpT_hi[(size_t)CC*CC];
__device__ __nv_bfloat16 g_wpT_lo[(size_t)CC*CC];
__device__ __nv_bfloat16 g_ahi[(size_t)NTOK*CC];
__device__ __nv_bfloat16 g_alo[(size_t)NTOK*CC];
// flash operands (head-major [bh][t][d]); q pre-scaled by 1/8
__device__ __nv_bfloat16 g_qh[(size_t)BH*TT*DD];
__device__ __nv_bfloat16 g_ql[(size_t)BH*TT*DD];
__device__ __nv_bfloat16 g_kh[(size_t)BH*TT*DD];
__device__ __nv_bfloat16 g_kl[(size_t)BH*TT*DD];
__device__ __nv_bfloat16 g_vh[(size_t)BH*TT*DD];
__device__ __nv_bfloat16 g_vl[(size_t)BH*TT*DD];

// ================= helpers =================
__device__ __forceinline__ uint32_t smem_u32(const void* p) {
    uint32_t a;
    asm("{ .reg .u64 t; cvta.to.shared.u64 t, %1; cvt.u32.u64 %0, t; }" : "=r"(a) : "l"(p));
    return a;
}
__device__ __forceinline__ void ldsm_x4(uint32_t& a0, uint32_t& a1, uint32_t& a2, uint32_t& a3, uint32_t addr) {
    asm volatile("ldmatrix.sync.aligned.m8n8.x4.shared.b16 {%0,%1,%2,%3}, [%4];"
                 : "=r"(a0), "=r"(a1), "=r"(a2), "=r"(a3) : "r"(addr));
}
__device__ __forceinline__ void ldsm_x2(uint32_t& b0, uint32_t& b1, uint32_t addr) {
    asm volatile("ldmatrix.sync.aligned.m8n8.x2.shared.b16 {%0,%1}, [%2];"
                 : "=r"(b0), "=r"(b1) : "r"(addr));
}
__device__ __forceinline__ void ldsm_x2t(uint32_t& b0, uint32_t& b1, uint32_t addr) {
    asm volatile("ldmatrix.sync.aligned.m8n8.x2.trans.shared.b16 {%0,%1}, [%2];"
                 : "=r"(b0), "=r"(b1) : "r"(addr));
}
__device__ __forceinline__ void mma_bf16(float* c, const uint32_t* a, const uint32_t* b) {
    asm volatile("mma.sync.aligned.m16n8k16.row.col.f32.bf16.bf16.f32 "
                 "{%0,%1,%2,%3}, {%4,%5,%6,%7}, {%8,%9}, {%0,%1,%2,%3};"
                 : "+f"(c[0]), "+f"(c[1]), "+f"(c[2]), "+f"(c[3])
                 : "r"(a[0]), "r"(a[1]), "r"(a[2]), "r"(a[3]), "r"(b[0]), "r"(b[1]));
}
#define CPASYNC16(dst, src) asm volatile("cp.async.cg.shared.global [%0], [%1], 16;" :: "r"(dst), "l"(src))
#define CPCOMMIT()          asm volatile("cp.async.commit_group;" ::: "memory")
#define CPWAIT(n)           asm volatile("cp.async.wait_group %0;" :: "n"(n) : "memory")

__device__ __forceinline__ uint32_t pack2(float x, float y) {
    __nv_bfloat162 t = __nv_bfloat162(__float2bfloat16(x), __float2bfloat16(y));
    return *(uint32_t*)&t;
}

// ================= cp.async double-buffered mma GEMM: C = A @ B^T + bias =================
// Pass-major MMA ordering: same-accumulator MMAs separated by 16 issues (no RAW chain stalls).
#define ROWB 80
#define BUFB (128 * ROWB)     /* 10240 */
#define STAGE (4 * BUFB)      /* 40960 */
#define GEMM_SMEM (2 * STAGE) /* 81920 */

__global__ __launch_bounds__(256) void mma_gemm_kernel(
    const __nv_bfloat16* __restrict__ Ahi, const __nv_bfloat16* __restrict__ Alo,
    const __nv_bfloat16* __restrict__ Bhi, const __nv_bfloat16* __restrict__ Blo,
    const float* __restrict__ bias, float* __restrict__ C,
    int M, int N, int K)
{
    extern __shared__ __align__(16) char dsm[];
    const int tid = threadIdx.x;
    const int wid = tid >> 5, lane = tid & 31;
    const int wm = wid & 1, wn = wid >> 1;
    const int m0 = blockIdx.y * 128, n0 = blockIdx.x * 128;
    const uint32_t ubase = smem_u32(dsm);

    float acc[4][4][4];
#pragma unroll
    for (int i = 0; i < 4; ++i)
#pragma unroll
        for (int j = 0; j < 4; ++j)
#pragma unroll
            for (int r = 0; r < 4; ++r) acc[i][j][r] = 0.f;

    const uint32_t aRow = (uint32_t)(lane & 15);
    const uint32_t aColSel = (uint32_t)(((lane >> 4) & 1) * 16);
    const uint32_t bRow = (uint32_t)(lane & 7);
    const uint32_t bColSel = (uint32_t)(((lane >> 3) & 1) * 16);

    const int id0 = tid, id1 = tid + 256;
    const int r0i = id0 >> 2, s0i = id0 & 3, r1i = id1 >> 2, s1i = id1 & 3;

    auto issue = [&](int kt, int sel) {
        const __nv_bfloat16* pa_hi = Ahi + (size_t)m0 * K + kt * 32;
        const __nv_bfloat16* pa_lo = Alo + (size_t)m0 * K + kt * 32;
        const __nv_bfloat16* pb_hi = Bhi + (size_t)n0 * K + kt * 32;
        const __nv_bfloat16* pb_lo = Blo + (size_t)n0 * K + kt * 32;
        uint32_t sb = ubase + sel * STAGE;
        {
            size_t go = (size_t)r0i * K + s0i * 8;
            uint32_t so = (uint32_t)(r0i * ROWB + s0i * 16);
            CPASYNC16(sb + so,            (const char*)(pa_hi + go));
            CPASYNC16(sb + BUFB + so,     (const char*)(pa_lo + go));
            CPASYNC16(sb + 2*BUFB + so,   (const char*)(pb_hi + go));
            CPASYNC16(sb + 3*BUFB + so,   (const char*)(pb_lo + go));
        }
        {
            size_t go = (size_t)r1i * K + s1i * 8;
            uint32_t so = (uint32_t)(r1i * ROWB + s1i * 16);
            CPASYNC16(sb + so,            (const char*)(pa_hi + go));
            CPASYNC16(sb + BUFB + so,     (const char*)(pa_lo + go));
            CPASYNC16(sb + 2*BUFB + so,   (const char*)(pb_hi + go));
            CPASYNC16(sb + 3*BUFB + so,   (const char*)(pb_lo + go));
        }
    };

    const int KT = K / 32;
    issue(0, 0);
    CPCOMMIT();

    for (int kt = 0; kt < KT; ++kt) {
        if (kt + 1 < KT) { issue(kt + 1, (kt + 1) & 1); CPCOMMIT(); CPWAIT(1); }
        else             { CPWAIT(0); }
        __syncthreads();

        uint32_t sb = ubase + (kt & 1) * STAGE;
        uint32_t uAhi = sb, uAlo = sb + BUFB, uBhi = sb + 2*BUFB, uBlo = sb + 3*BUFB;
#pragma unroll
        for (int kh = 0; kh < 2; ++kh) {
            uint32_t ahi[4][4], alo[4][4], bhi[4][2], blo[4][2];
#pragma unroll
            for (int mt = 0; mt < 4; ++mt) {
                uint32_t off = (uint32_t)((wm * 64 + mt * 16 + aRow) * ROWB) + kh * 32 + aColSel;
                ldsm_x4(ahi[mt][0], ahi[mt][1], ahi[mt][2], ahi[mt][3], uAhi + off);
                ldsm_x4(alo[mt][0], alo[mt][1], alo[mt][2], alo[mt][3], uAlo + off);
            }
#pragma unroll
            for (int nt = 0; nt < 4; ++nt) {
                uint32_t off = (uint32_t)((wn * 32 + nt * 8 + bRow) * ROWB) + kh * 32 + bColSel;
                ldsm_x2(bhi[nt][0], bhi[nt][1], uBhi + off);
                ldsm_x2(blo[nt][0], blo[nt][1], uBlo + off);
            }
            // pass-major: same-acc MMAs are 16 issues apart
#pragma unroll
            for (int mt = 0; mt < 4; ++mt)
#pragma unroll
                for (int nt = 0; nt < 4; ++nt)
                    mma_bf16(acc[mt][nt], ahi[mt], bhi[nt]);
#pragma unroll
            for (int mt = 0; mt < 4; ++mt)
#pragma unroll
                for (int nt = 0; nt < 4; ++nt)
                    mma_bf16(acc[mt][nt], ahi[mt], blo[nt]);
#pragma unroll
            for (int mt = 0; mt < 4; ++mt)
#pragma unroll
                for (int nt = 0; nt < 4; ++nt)
                    mma_bf16(acc[mt][nt], alo[mt], bhi[nt]);
        }
        __syncthreads();
    }

    const int rbase = m0 + wm * 64 + (lane >> 2);
    const int cbase = n0 + wn * 32 + (lane & 3) * 2;
#pragma unroll
    for (int mt = 0; mt < 4; ++mt)
#pragma unroll
        for (int nt = 0; nt < 4; ++nt) {
            int r = rbase + mt * 16;
            int c = cbase + nt * 8;
            float2 bv = *(const float2*)(bias + c);
            float2 o0 = { acc[mt][nt][0] + bv.x, acc[mt][nt][1] + bv.y };
            float2 o1 = { acc[mt][nt][2] + bv.x, acc[mt][nt][3] + bv.y };
            *(float2*)(C + (size_t)r * N + c) = o0;
            *(float2*)(C + (size_t)(r + 8) * N + c) = o1;
        }
}

// ================= tensor-core flash attention (cp.async 2-stage, fused split epilogue) =================
// Pass-major MMA ordering in nt-groups of 4 (same-acc distance 4 issues).
#define FROWB 144
#define FBUF (64 * FROWB)     /* 9216 */
#define FSTAGE (4 * FBUF)     /* 36864 */
#define FL_SMEM (2 * FSTAGE)  /* 73728 */

__global__ __launch_bounds__(256) void flash_tc_kernel(
    const __nv_bfloat16* __restrict__ qh, const __nv_bfloat16* __restrict__ ql,
    const __nv_bfloat16* __restrict__ kh, const __nv_bfloat16* __restrict__ kl,
    const __nv_bfloat16* __restrict__ vh, const __nv_bfloat16* __restrict__ vl,
    __nv_bfloat16* __restrict__ ahi, __nv_bfloat16* __restrict__ alo)
{
    extern __shared__ __align__(16) char fsm[];
    const uint32_t ubase = smem_u32(fsm);

    const int qt = blockIdx.x;
    const int bh = blockIdx.y;
    const int tid = threadIdx.x;
    const int wid = tid >> 5, lane = tid & 31;
    const int Q0 = qt * 128;
    const int rowbase = Q0 + wid * 16;

    // ---- stage Q into stage-0 buffers (rows0-63 -> K bufs, rows64-127 -> V bufs) ----
    {
        const __nv_bfloat16* qbh = qh + ((size_t)bh * TT + Q0) * DD;
        const __nv_bfloat16* qbl = ql + ((size_t)bh * TT + Q0) * DD;
#pragma unroll
        for (int it = 0; it < 4; ++it) {
            int id = tid + it * 256;
            int row = id >> 3, seg = id & 7;
            size_t go = (size_t)row * DD + seg * 8;
            int drow = row & 63;
            uint32_t dh = ubase + ((row < 64) ? 0 : 2 * FBUF) + drow * FROWB + seg * 16;
            uint32_t dl = dh + FBUF;
            *(uint4*)(fsm + (dh - ubase)) = *(const uint4*)(qbh + go);
            *(uint4*)(fsm + (dl - ubase)) = *(const uint4*)(qbl + go);
        }
    }
    __syncthreads();

    // Q fragments (persist in regs)
    uint32_t qfh[4][4], qfl[4][4];
    {
        uint32_t bufh = ubase + ((wid < 4) ? 0 : 2 * FBUF);
        uint32_t bufl = bufh + FBUF;
        uint32_t rsel = (uint32_t)(((wid & 3) * 16 + (lane & 15)) * FROWB);
        uint32_t csel = (uint32_t)(((lane >> 4) & 1) * 16);
#pragma unroll
        for (int kc = 0; kc < 4; ++kc) {
            uint32_t off = rsel + kc * 32 + csel;
            ldsm_x4(qfh[kc][0], qfh[kc][1], qfh[kc][2], qfh[kc][3], bufh + off);
            ldsm_x4(qfl[kc][0], qfl[kc][1], qfl[kc][2], qfl[kc][3], bufl + off);
        }
    }
    __syncthreads();

    float mrow0 = -1e30f, mrow1 = -1e30f, lrow0 = 0.f, lrow1 = 0.f;
    float O[8][4];
#pragma unroll
    for (int nt = 0; nt < 8; ++nt)
#pragma unroll
        for (int j = 0; j < 4; ++j) O[nt][j] = 0.f;

    const uint32_t kRow = (uint32_t)(lane & 7);
    const uint32_t kColSel = (uint32_t)(((lane >> 3) & 1) * 16);
    const int nsteps = qt * 2 + 2;

    const int idA = tid, idB = tid + 256;
    const int rA = idA >> 3, sA = idA & 7, rB = idB >> 3, sB = idB & 7;

    auto issue = [&](int s, int sel) {
        const int kv0 = s * 64;
        const __nv_bfloat16* pkh = kh + ((size_t)bh * TT + kv0) * DD;
        const __nv_bfloat16* pkl = kl + ((size_t)bh * TT + kv0) * DD;
        const __nv_bfloat16* pvh = vh + ((size_t)bh * TT + kv0) * DD;
        const __nv_bfloat16* pvl = vl + ((size_t)bh * TT + kv0) * DD;
        uint32_t sb = ubase + sel * FSTAGE;
        {
            size_t go = (size_t)rA * DD + sA * 8;
            uint32_t so = (uint32_t)(rA * FROWB + sA * 16);
            CPASYNC16(sb + so,            (const char*)(pkh + go));
            CPASYNC16(sb + FBUF + so,     (const char*)(pkl + go));
            CPASYNC16(sb + 2*FBUF + so,   (const char*)(pvh + go));
            CPASYNC16(sb + 3*FBUF + so,   (const char*)(pvl + go));
        }
        {
            size_t go = (size_t)rB * DD + sB * 8;
            uint32_t so = (uint32_t)(rB * FROWB + sB * 16);
            CPASYNC16(sb + so,            (const char*)(pkh + go));
            CPASYNC16(sb + FBUF + so,     (const char*)(pkl + go));
            CPASYNC16(sb + 2*FBUF + so,   (const char*)(pvh + go));
            CPASYNC16(sb + 3*FBUF + so,   (const char*)(pvl + go));
        }
    };

    issue(0, 0);
    CPCOMMIT();

    for (int s = 0; s < nsteps; ++s) {
        const int kv0 = s * 64;
        if (s + 1 < nsteps) { issue(s + 1, (s + 1) & 1); CPCOMMIT(); CPWAIT(1); }
        else                { CPWAIT(0); }
        __syncthreads();

        uint32_t sb = ubase + (s & 1) * FSTAGE;
        uint32_t uKhi = sb, uKlo = sb + FBUF, uVhi = sb + 2*FBUF, uVlo = sb + 3*FBUF;

        // ---- S = Q K^T (split 3-pass, pass-major in nt-groups of 4) ----
        float S[8][4];
#pragma unroll
        for (int nt = 0; nt < 8; ++nt)
#pragma unroll
            for (int j = 0; j < 4; ++j) S[nt][j] = 0.f;
#pragma unroll
        for (int kc = 0; kc < 4; ++kc) {
#pragma unroll
            for (int g = 0; g < 2; ++g) {
                uint32_t kbh[4][2], kbl[4][2];
#pragma unroll
                for (int j = 0; j < 4; ++j) {
                    int nt = g * 4 + j;
                    uint32_t off = (uint32_t)((nt * 8 + kRow) * FROWB) + kc * 32 + kColSel;
                    ldsm_x2(kbh[j][0], kbh[j][1], uKhi + off);
                    ldsm_x2(kbl[j][0], kbl[j][1], uKlo + off);
                }
#pragma unroll
                for (int j = 0; j < 4; ++j) mma_bf16(S[g * 4 + j], qfh[kc], kbh[j]);
#pragma unroll
                for (int j = 0; j < 4; ++j) mma_bf16(S[g * 4 + j], qfh[kc], kbl[j]);
#pragma unroll
                for (int j = 0; j < 4; ++j) mma_bf16(S[g * 4 + j], qfl[kc], kbh[j]);
            }
        }

        // ---- causal mask ----
        if (kv0 + 63 > rowbase) {
            int r0 = rowbase + (lane >> 2), r1 = r0 + 8;
            int cb = kv0 + 2 * (lane & 3);
#pragma unroll
            for (int nt = 0; nt < 8; ++nt) {
                int c0 = cb + nt * 8, c1 = c0 + 1;
                if (c0 > r0) S[nt][0] = -1e30f;
                if (c1 > r0) S[nt][1] = -1e30f;
                if (c0 > r1) S[nt][2] = -1e30f;
                if (c1 > r1) S[nt][3] = -1e30f;
            }
        }

        // ---- online softmax (per-warp, register-only) ----
        float mx0 = -1e30f, mx1 = -1e30f;
#pragma unroll
        for (int nt = 0; nt < 8; ++nt) {
            mx0 = fmaxf(mx0, fmaxf(S[nt][0], S[nt][1]));
            mx1 = fmaxf(mx1, fmaxf(S[nt][2], S[nt][3]));
        }
        mx0 = fmaxf(mx0, __shfl_xor_sync(0xffffffffu, mx0, 1));
        mx0 = fmaxf(mx0, __shfl_xor_sync(0xffffffffu, mx0, 2));
        mx1 = fmaxf(mx1, __shfl_xor_sync(0xffffffffu, mx1, 1));
        mx1 = fmaxf(mx1, __shfl_xor_sync(0xffffffffu, mx1, 2));
        float mn0 = fmaxf(mrow0, mx0), mn1 = fmaxf(mrow1, mx1);
        float a0 = __expf(mrow0 - mn0), a1 = __expf(mrow1 - mn1);
        float rs0 = 0.f, rs1 = 0.f;
#pragma unroll
        for (int nt = 0; nt < 8; ++nt) {
            S[nt][0] = __expf(S[nt][0] - mn0); rs0 += S[nt][0];
            S[nt][1] = __expf(S[nt][1] - mn0); rs0 += S[nt][1];
            S[nt][2] = __expf(S[nt][2] - mn1); rs1 += S[nt][2];
            S[nt][3] = __expf(S[nt][3] - mn1); rs1 += S[nt][3];
        }
        rs0 += __shfl_xor_sync(0xffffffffu, rs0, 1);
        rs0 += __shfl_xor_sync(0xffffffffu, rs0, 2);
        rs1 += __shfl_xor_sync(0xffffffffu, rs1, 1);
        rs1 += __shfl_xor_sync(0xffffffffu, rs1, 2);
        lrow0 = lrow0 * a0 + rs0;
        lrow1 = lrow1 * a1 + rs1;
        mrow0 = mn0; mrow1 = mn1;
#pragma unroll
        for (int nt = 0; nt < 8; ++nt) {
            O[nt][0] *= a0; O[nt][1] *= a0; O[nt][2] *= a1; O[nt][3] *= a1;
        }

        // ---- O += P V (split 3-pass, pass-major in nt-groups of 4) ----
#pragma unroll
        for (int kc = 0; kc < 4; ++kc) {
            int t0 = 2 * kc, t1 = 2 * kc + 1;
            uint32_t phi[4], plo[4];
            phi[0] = pack2(S[t0][0], S[t0][1]);
            phi[1] = pack2(S[t0][2], S[t0][3]);
            phi[2] = pack2(S[t1][0], S[t1][1]);
            phi[3] = pack2(S[t1][2], S[t1][3]);
            plo[0] = pack2(S[t0][0] - __bfloat162float(__float2bfloat16(S[t0][0])),
                           S[t0][1] - __bfloat162float(__float2bfloat16(S[t0][1])));
            plo[1] = pack2(S[t0][2] - __bfloat162float(__float2bfloat16(S[t0][2])),
                           S[t0][3] - __bfloat162float(__float2bfloat16(S[t0][3])));
            plo[2] = pack2(S[t1][0] - __bfloat162float(__float2bfloat16(S[t1][0])),
                           S[t1][1] - __bfloat162float(__float2bfloat16(S[t1][1])));
            plo[3] = pack2(S[t1][2] - __bfloat162float(__float2bfloat16(S[t1][2])),
                           S[t1][3] - __bfloat162float(__float2bfloat16(S[t1][3])));
            uint32_t vRow = (uint32_t)((kc * 16 + (lane & 15)) * FROWB);
#pragma unroll
            for (int g = 0; g < 2; ++g) {
                uint32_t vbh[4][2], vbl[4][2];
#pragma unroll
                for (int j = 0; j < 4; ++j) {
                    uint32_t off = vRow + (g * 4 + j) * 16;
                    ldsm_x2t(vbh[j][0], vbh[j][1], uVhi + off);
                    ldsm_x2t(vbl[j][0], vbl[j][1], uVlo + off);
                }
#pragma unroll
                for (int j = 0; j < 4; ++j) mma_bf16(O[g * 4 + j], phi, vbh[j]);
#pragma unroll
                for (int j = 0; j < 4; ++j) mma_bf16(O[g * 4 + j], phi, vbl[j]);
#pragma unroll
                for (int j = 0; j < 4; ++j) mma_bf16(O[g * 4 + j], plo, vbh[j]);
            }
        }
        __syncthreads();
    }

    // ---- fused epilogue: write split bf16 attn (hi/lo) directly ----
    const int b = bh >> 4, hh = bh & 15;
    const float il0 = 1.0f / lrow0, il1 = 1.0f / lrow1;
    const int r0 = rowbase + (lane >> 2);
    const size_t tok0 = (size_t)b * TT + r0;
#pragma unroll
    for (int nt = 0; nt < 8; ++nt) {
        int c = hh * DD + nt * 8 + 2 * (lane & 3);
        float o00 = O[nt][0] * il0, o01 = O[nt][1] * il0;
        float o10 = O[nt][2] * il1, o11 = O[nt][3] * il1;
        float h00 = __bfloat162float(__float2bfloat16(o00));
        float h01 = __bfloat162float(__float2bfloat16(o01));
        float h10 = __bfloat162float(__float2bfloat16(o10));
        float h11 = __bfloat162float(__float2bfloat16(o11));
        *(uint32_t*)(ahi + tok0 * CC + c)       = pack2(o00, o01);
        *(uint32_t*)(alo + tok0 * CC + c)       = pack2(o00 - h00, o01 - h01);
        *(uint32_t*)(ahi + (tok0 + 8) * CC + c) = pack2(o10, o11);
        *(uint32_t*)(alo + (tok0 + 8) * CC + c) = pack2(o10 - h10, o11 - h11);
    }
}

// ================= split fp32 -> (hi, lo) bf16 =================
__global__ __launch_bounds__(256) void split_kernel(
    const float* __restrict__ src, __nv_bfloat16* __restrict__ hi,
    __nv_bfloat16* __restrict__ lo, size_t n4)
{
    size_t i = (size_t)blockIdx.x * blockDim.x + threadIdx.x;
    if (i >= n4) return;
    float4 v = ((const float4*)src)[i];
    __nv_bfloat16 h0 = __float2bfloat16(v.x), h1 = __float2bfloat16(v.y);
    __nv_bfloat16 h2 = __float2bfloat16(v.z), h3 = __float2bfloat16(v.w);
    __nv_bfloat16 l0 = __float2bfloat16(v.x - __bfloat162float(h0));
    __nv_bfloat16 l1 = __float2bfloat16(v.y - __bfloat162float(h1));
    __nv_bfloat16 l2 = __float2bfloat16(v.z - __bfloat162float(h2));
    __nv_bfloat16 l3 = __float2bfloat16(v.w - __bfloat162float(h3));
    ((__nv_bfloat162*)hi)[2 * i]     = __nv_bfloat162(h0, h1);
    ((__nv_bfloat162*)hi)[2 * i + 1] = __nv_bfloat162(h2, h3);
    ((__nv_bfloat162*)lo)[2 * i]     = __nv_bfloat162(l0, l1);
    ((__nv_bfloat162*)lo)[2 * i + 1] = __nv_bfloat162(l2, l3);
}

// ================= transpose + split weights =================
__global__ __launch_bounds__(256) void transpose_split_kernel(
    const float* __restrict__ W, __nv_bfloat16* __restrict__ hi,
    __nv_bfloat16* __restrict__ lo, int K, int N)
{
    __shared__ float t[32][33];
    int tx = threadIdx.x, ty = threadIdx.y;
    int n0 = blockIdx.x * 32, k0 = blockIdx.y * 32;
#pragma unroll
    for (int i = 0; i < 4; ++i)
        t[ty + i * 8][tx] = W[(size_t)(k0 + ty + i * 8) * N + n0 + tx];
    __syncthreads();
#pragma unroll
    for (int i = 0; i < 4; ++i) {
        int n = n0 + ty + i * 8, k = k0 + tx;
        float v = t[tx][ty + i * 8];
        __nv_bfloat16 h = __float2bfloat16(v);
        hi[(size_t)n * K + k] = h;
        lo[(size_t)n * K + k] = __float2bfloat16(v - __bfloat162float(h));
    }
}

// ================= RMSNorm + RoPE -> split bf16 outputs + direct value write =================
__global__ __launch_bounds__(256) void rmsrope_kernel(
    const float* __restrict__ qkv,
    __nv_bfloat16* __restrict__ qhi, __nv_bfloat16* __restrict__ qlo,
    __nv_bfloat16* __restrict__ khi, __nv_bfloat16* __restrict__ klo,
    __nv_bfloat16* __restrict__ vhi, __nv_bfloat16* __restrict__ vlo,
    float* __restrict__ vout)
{
    int gw   = (int)((blockIdx.x * blockDim.x + threadIdx.x) >> 5);
    int lane = threadIdx.x & 31;
    if (gw >= BH * TT) return;
    int t = gw % TT;
    int h = (gw / TT) % HH;
    int b = gw / (TT * HH);

    size_t tok = (size_t)b * TT + t;
    const float* base = qkv + tok * C3 + h * DD;
    size_t oidx = ((size_t)(b * HH + h) * TT + t) * DD;

    float ex  = (float)lane * (1.0f / 32.0f);
    float inv = expf(-ex * 9.210340371976184f);
    float ang = (float)t * inv;
    float cs, sn;
    sincosf(ang, &cs, &sn);

    // q (scaled by 1/8 before split)
    {
        float x1 = base[lane], x2 = base[lane + 32];
        float ss = x1 * x1 + x2 * x2;
#pragma unroll
        for (int off = 16; off; off >>= 1) ss += __shfl_xor_sync(0xffffffffu, ss, off);
        float r = rsqrtf(ss * (1.0f / 64.0f) + 1e-6f) * 0.125f;
        x1 *= r; x2 *= r;
        float o1 = x1 * cs - x2 * sn;
        float o2 = x1 * sn + x2 * cs;
        __nv_bfloat16 h1 = __float2bfloat16(o1), h2 = __float2bfloat16(o2);
        qhi[oidx + lane]      = h1;
        qhi[oidx + lane + 32] = h2;
        qlo[oidx + lane]      = __float2bfloat16(o1 - __bfloat162float(h1));
        qlo[oidx + lane + 32] = __float2bfloat16(o2 - __bfloat162float(h2));
    }
    // k
    {
        const float* kb = base + CC;
        float x1 = kb[lane], x2 = kb[lane + 32];
        float ss = x1 * x1 + x2 * x2;
#pragma unroll
        for (int off = 16; off; off >>= 1) ss += __shfl_xor_sync(0xffffffffu, ss, off);
        float r = rsqrtf(ss * (1.0f / 64.0f) + 1e-6f);
        x1 *= r; x2 *= r;
        float o1 = x1 * cs - x2 * sn;
        float o2 = x1 * sn + x2 * cs;
        __nv_bfloat16 h1 = __float2bfloat16(o1), h2 = __float2bfloat16(o2);
        khi[oidx + lane]      = h1;
        khi[oidx + lane + 32] = h2;
        klo[oidx + lane]      = __float2bfloat16(o1 - __bfloat162float(h1));
        klo[oidx + lane + 32] = __float2bfloat16(o2 - __bfloat162float(h2));
    }
    // v: direct fp32 value output + split
    {
        float v1 = base[2 * CC + lane], v2 = base[2 * CC + lane + 32];
        vout[oidx + lane]      = v1;
        vout[oidx + lane + 32] = v2;
        __nv_bfloat16 h1 = __float2bfloat16(v1), h2 = __float2bfloat16(v2);
        vhi[oidx + lane]      = h1;
        vhi[oidx + lane + 32] = h2;
        vlo[oidx + lane]      = __float2bfloat16(v1 - __bfloat162float(h1));
        vlo[oidx + lane + 32] = __float2bfloat16(v2 - __bfloat162float(h2));
    }
}

// ================= launch =================
extern "C" void kernel_launch(void* const* d_in, const int* in_sizes, int n_in,
                              void* d_out, int out_size)
{
    const float* x = nullptr; const float* Wqkv = nullptr; const float* bqkv = nullptr;
    const float* Wproj = nullptr; const float* bproj = nullptr;
    for (int i = 0; i < n_in; ++i) {
        switch (in_sizes[i]) {
            case 8388608: x     = (const float*)d_in[i]; break;
            case 3145728: Wqkv  = (const float*)d_in[i]; break;
            case 3072:    bqkv  = (const float*)d_in[i]; break;
            case 1048576: Wproj = (const float*)d_in[i]; break;
            case 1024:    bproj = (const float*)d_in[i]; break;
            default: break; // lamb: exact identity, unused
        }
    }

    float* out = (float*)d_out;

    float *qkv, *vn;
    __nv_bfloat16 *xhi, *xlo, *wqhi, *wqlo, *wphi, *wplo, *ahi, *alo;
    __nv_bfloat16 *qh_, *ql_, *kh_, *kl_, *vh_, *vl_;
    cudaGetSymbolAddress((void**)&qkv, g_qkv);
    cudaGetSymbolAddress((void**)&vn,  g_vn);
    cudaGetSymbolAddress((void**)&xhi, g_xhi);
    cudaGetSymbolAddress((void**)&xlo, g_xlo);
    cudaGetSymbolAddress((void**)&wqhi, g_wqT_hi);
    cudaGetSymbolAddress((void**)&wqlo, g_wqT_lo);
    cudaGetSymbolAddress((void**)&wphi, g_wpT_hi);
    cudaGetSymbolAddress((void**)&wplo, g_wpT_lo);
    cudaGetSymbolAddress((void**)&ahi, g_ahi);
    cudaGetSymbolAddress((void**)&alo, g_alo);
    cudaGetSymbolAddress((void**)&qh_, g_qh);
    cudaGetSymbolAddress((void**)&ql_, g_ql);
    cudaGetSymbolAddress((void**)&kh_, g_kh);
    cudaGetSymbolAddress((void**)&kl_, g_kl);
    cudaGetSymbolAddress((void**)&vh_, g_vh);
    cudaGetSymbolAddress((void**)&vl_, g_vl);

    cudaFuncSetAttribute(mma_gemm_kernel, cudaFuncAttributeMaxDynamicSharedMemorySize, GEMM_SMEM);
    cudaFuncSetAttribute(flash_tc_kernel, cudaFuncAttributeMaxDynamicSharedMemorySize, FL_SMEM);

    // value output target: directly into d_out's second tuple slot if present
    float* value_out = ((size_t)out_size >= 2 * OUT0_ELEMS) ? (out + OUT0_ELEMS) : vn;

    // 0) operand prep
    {
        size_t n4 = ((size_t)NTOK * CC) / 4;
        split_kernel<<<(unsigned)((n4 + 255) / 256), 256>>>(x, xhi, xlo, n4);
    }
    transpose_split_kernel<<<dim3(C3 / 32, CC / 32), dim3(32, 8)>>>(Wqkv, wqhi, wqlo, CC, C3);
    transpose_split_kernel<<<dim3(CC / 32, CC / 32), dim3(32, 8)>>>(Wproj, wphi, wplo, CC, CC);

    // 1) QKV = x @ Wqkv + bqkv
    mma_gemm_kernel<<<dim3(C3 / 128, NTOK / 128), 256, GEMM_SMEM>>>(
        xhi, xlo, wqhi, wqlo, bqkv, qkv, NTOK, C3, CC);

    // 2) rmsnorm + rope -> split bf16 q/k/v; value written directly to output
    rmsrope_kernel<<<(BH * TT) / 8, 256>>>(qkv, qh_, ql_, kh_, kl_, vh_, vl_, value_out);

    // 3) tensor-core causal flash attention (fused split epilogue -> ahi/alo)
    flash_tc_kernel<<<dim3(TT / 128, BH), 256, FL_SMEM>>>(qh_, ql_, kh_, kl_, vh_, vl_, ahi, alo);

    // 4) out = attn @ Wproj + bproj
    mma_gemm_kernel<<<dim3(CC / 128, NTOK / 128), 256, GEMM_SMEM>>>(
        ahi, alo, wphi, wplo, bproj, out, NTOK, CC, CC);
}